// round 3
// baseline (speedup 1.0000x reference)
#include <cuda_runtime.h>
#include <cuda_bf16.h>
#include <cstdint>

#define B_   4
#define S_   2048
#define H_   16
#define D_   64
#define HID  1024
#define M_   (B_ * S_)

__device__ float g_Q[B_ * H_ * S_ * D_];
__device__ float g_K[B_ * H_ * S_ * D_];
__device__ float g_V[B_ * H_ * S_ * D_];

__device__ __forceinline__ uint32_t f2tf(float x) {
    uint32_t r;
    asm("cvt.rna.tf32.f32 %0, %1;" : "=r"(r) : "f"(x));
    return r;
}

#define MMA_TF32(c, a, b)                                              \
    asm volatile(                                                      \
        "mma.sync.aligned.m16n8k8.row.col.f32.tf32.tf32.f32 "          \
        "{%0,%1,%2,%3}, {%4,%5,%6,%7}, {%8,%9}, {%0,%1,%2,%3};\n"      \
        : "+f"((c)[0]), "+f"((c)[1]), "+f"((c)[2]), "+f"((c)[3])       \
        : "r"((a)[0]), "r"((a)[1]), "r"((a)[2]), "r"((a)[3]),          \
          "r"((b)[0]), "r"((b)[1]))

// ---------------------------------------------------------------------------
// Kernel A: fused QKV tf32 GEMM. grid.z selects Q/K/V.
// 128x128 block, BK=32, 128 threads = 4 warps (2x2), warp tile 64x64.
// LDS/mma ratio = 1.0 (16 A-regs + 16 B-regs per 32 mmas per k8-step).
// ---------------------------------------------------------------------------
#define AS_STRIDE 36   // A-frag bank = 4*grp + thr  -> conflict-free
#define BS_STRIDE 136  // B-frag bank = 8*thr + grp  -> conflict-free

__global__ __launch_bounds__(128) void qkv_gemm3(const float* __restrict__ X,
                                                 const float* __restrict__ Wq,
                                                 const float* __restrict__ Wk,
                                                 const float* __restrict__ Wv,
                                                 const float* __restrict__ bq,
                                                 const float* __restrict__ bk,
                                                 const float* __restrict__ bv,
                                                 float* __restrict__ oQ,
                                                 float* __restrict__ oK,
                                                 float* __restrict__ oV)
{
    __shared__ uint32_t As[128 * AS_STRIDE];
    __shared__ uint32_t Bs[32 * BS_STRIDE];

    const int z = blockIdx.z;
    const float* W    = (z == 0) ? Wq : (z == 1) ? Wk : Wv;
    const float* bias = (z == 0) ? bq : (z == 1) ? bk : bv;
    float* outh       = (z == 0) ? oQ : (z == 1) ? oK : oV;

    const int tid  = threadIdx.x;
    const int warp = tid >> 5;
    const int lane = tid & 31;
    const int grp  = lane >> 2;
    const int thr  = lane & 3;
    const int wm   = warp >> 1;   // 0..1
    const int wn   = warp & 1;    // 0..1
    const int m0   = blockIdx.y * 128;
    const int n0   = blockIdx.x * 128;

    float acc[4][8][4];
    #pragma unroll
    for (int mt = 0; mt < 4; ++mt)
        #pragma unroll
        for (int nt = 0; nt < 8; ++nt)
            #pragma unroll
            for (int r = 0; r < 4; ++r) acc[mt][nt][r] = 0.f;

    for (int k0 = 0; k0 < HID; k0 += 32) {
        __syncthreads();
        // stage A (128x32) and B (32x128), fully coalesced float4 loads
        #pragma unroll
        for (int t = 0; t < 8; ++t) {
            int i  = tid + t * 128;
            int ar = i >> 3, ac = (i & 7) * 4;
            float4 av = *reinterpret_cast<const float4*>(&X[(size_t)(m0 + ar) * HID + k0 + ac]);
            uint4 au = {f2tf(av.x), f2tf(av.y), f2tf(av.z), f2tf(av.w)};
            *reinterpret_cast<uint4*>(&As[ar * AS_STRIDE + ac]) = au;
            int br = i >> 5, bc = (i & 31) * 4;
            float4 bv4 = *reinterpret_cast<const float4*>(&W[(size_t)(k0 + br) * HID + n0 + bc]);
            uint4 bu = {f2tf(bv4.x), f2tf(bv4.y), f2tf(bv4.z), f2tf(bv4.w)};
            *reinterpret_cast<uint4*>(&Bs[br * BS_STRIDE + bc]) = bu;
        }
        __syncthreads();

        #pragma unroll
        for (int kk = 0; kk < 32; kk += 8) {
            uint32_t a[4][4], b[8][2];
            #pragma unroll
            for (int mt = 0; mt < 4; ++mt) {
                int r = wm * 64 + mt * 16 + grp;
                a[mt][0] = As[r * AS_STRIDE + kk + thr];
                a[mt][1] = As[(r + 8) * AS_STRIDE + kk + thr];
                a[mt][2] = As[r * AS_STRIDE + kk + thr + 4];
                a[mt][3] = As[(r + 8) * AS_STRIDE + kk + thr + 4];
            }
            #pragma unroll
            for (int nt = 0; nt < 8; ++nt) {
                int c = wn * 64 + nt * 8 + grp;
                b[nt][0] = Bs[(kk + thr) * BS_STRIDE + c];
                b[nt][1] = Bs[(kk + thr + 4) * BS_STRIDE + c];
            }
            #pragma unroll
            for (int mt = 0; mt < 4; ++mt)
                #pragma unroll
                for (int nt = 0; nt < 8; ++nt)
                    MMA_TF32(acc[mt][nt], a[mt], b[nt]);
        }
    }

    // Epilogue: bias + scatter to [B,H,S,Dh], float2 stores
    #pragma unroll
    for (int mt = 0; mt < 4; ++mt) {
        #pragma unroll
        for (int half = 0; half < 2; ++half) {
            int m = m0 + wm * 64 + mt * 16 + grp + half * 8;
            int bb = m >> 11, s = m & 2047;
            #pragma unroll
            for (int nt = 0; nt < 8; ++nt) {
                int n = n0 + wn * 64 + nt * 8 + 2 * thr;
                int h = n >> 6, d = n & 63;
                float2 v = {acc[mt][nt][half * 2 + 0] + bias[n],
                            acc[mt][nt][half * 2 + 1] + bias[n + 1]};
                *reinterpret_cast<float2*>(
                    &outh[(((size_t)(bb * H_ + h) * S_) + s) * D_ + d]) = v;
            }
        }
    }
}

// ---------------------------------------------------------------------------
// Kernel B: flash attention, tf32 mma. Block = (b, h, 128-query tile),
// 128 threads = 4 warps, warp tile Mw=32 (two 16-row A-tiles), Bkv=64.
// ---------------------------------------------------------------------------
#define QS 68    // A-frag bank = 4*grp + thr
#define KS 68    // B-frag bank = 4*grp + thr
#define VSS 72   // B-frag bank = 8*thr + grp
#define STS_ 68

__global__ __launch_bounds__(128) void attn_tf32(const float* __restrict__ Q,
                                                 const float* __restrict__ K,
                                                 const float* __restrict__ V,
                                                 const float* __restrict__ mask,
                                                 float* __restrict__ out)
{
    extern __shared__ uint32_t sm[];
    uint32_t* Qs = sm;                     // [128][QS] tf32, prescaled
    uint32_t* Ks = Qs + 128 * QS;          // [64][KS]
    uint32_t* Vs = Ks + 64 * KS;           // [64][VSS]
    uint32_t* St = Vs + 64 * VSS;          // [128][STS_] probs tf32
    float*   msk = (float*)(St + 128 * STS_);  // [64]

    const int tid  = threadIdx.x;
    const int warp = tid >> 5;
    const int lane = tid & 31;
    const int grp  = lane >> 2;
    const int thr  = lane & 3;
    const int q0   = blockIdx.x * 128;
    const int h    = blockIdx.y;
    const int b    = blockIdx.z;
    const size_t base = (size_t)(b * H_ + h) * S_ * D_;
    const int wr0 = warp * 32;

    // Load Q tile (128 rows), prescale by 1/8 (exact), convert tf32
    #pragma unroll
    for (int t = 0; t < 16; ++t) {
        int i = tid + t * 128;
        int r = i >> 4, c = (i & 15) * 4;
        float4 v = *reinterpret_cast<const float4*>(&Q[base + (size_t)(q0 + r) * D_ + c]);
        uint4 u = {f2tf(v.x * 0.125f), f2tf(v.y * 0.125f),
                   f2tf(v.z * 0.125f), f2tf(v.w * 0.125f)};
        *reinterpret_cast<uint4*>(&Qs[r * QS + c]) = u;
    }

    float mrun[4] = {-1e30f, -1e30f, -1e30f, -1e30f};
    float lrun[4] = {0.f, 0.f, 0.f, 0.f};
    float o[2][8][4];
    #pragma unroll
    for (int at = 0; at < 2; ++at)
        #pragma unroll
        for (int nt = 0; nt < 8; ++nt)
            #pragma unroll
            for (int r = 0; r < 4; ++r) o[at][nt][r] = 0.f;

    for (int k0 = 0; k0 < S_; k0 += 64) {
        __syncthreads();   // prior iter's consumers of Ks/Vs/St done
        #pragma unroll
        for (int t = 0; t < 8; ++t) {
            int i = tid + t * 128;
            int r = i >> 4, c = (i & 15) * 4;
            float4 kv = *reinterpret_cast<const float4*>(&K[base + (size_t)(k0 + r) * D_ + c]);
            uint4 ku = {f2tf(kv.x), f2tf(kv.y), f2tf(kv.z), f2tf(kv.w)};
            *reinterpret_cast<uint4*>(&Ks[r * KS + c]) = ku;
            float4 vv = *reinterpret_cast<const float4*>(&V[base + (size_t)(k0 + r) * D_ + c]);
            uint4 vu = {f2tf(vv.x), f2tf(vv.y), f2tf(vv.z), f2tf(vv.w)};
            *reinterpret_cast<uint4*>(&Vs[r * VSS + c]) = vu;
        }
        if (tid < 64) msk[tid] = mask[b * S_ + k0 + tid];
        __syncthreads();

        // ---- S = Q @ K^T : B-frags shared across both A-tiles ----
        float s[2][8][4];
        #pragma unroll
        for (int at = 0; at < 2; ++at)
            #pragma unroll
            for (int nt = 0; nt < 8; ++nt)
                #pragma unroll
                for (int r = 0; r < 4; ++r) s[at][nt][r] = 0.f;

        #pragma unroll
        for (int kk = 0; kk < 64; kk += 8) {
            uint32_t bfr[8][2];
            #pragma unroll
            for (int nt = 0; nt < 8; ++nt) {
                int key = nt * 8 + grp;
                bfr[nt][0] = Ks[key * KS + kk + thr];
                bfr[nt][1] = Ks[key * KS + kk + thr + 4];
            }
            #pragma unroll
            for (int at = 0; at < 2; ++at) {
                int r0 = wr0 + at * 16 + grp;
                uint32_t a[4];
                a[0] = Qs[r0 * QS + kk + thr];
                a[1] = Qs[(r0 + 8) * QS + kk + thr];
                a[2] = Qs[r0 * QS + kk + thr + 4];
                a[3] = Qs[(r0 + 8) * QS + kk + thr + 4];
                #pragma unroll
                for (int nt = 0; nt < 8; ++nt)
                    MMA_TF32(s[at][nt], a, bfr[nt]);
            }
        }

        // ---- mask + online softmax + stage P ----
        #pragma unroll
        for (int at = 0; at < 2; ++at) {
            float rmax0 = -1e30f, rmax1 = -1e30f;
            #pragma unroll
            for (int nt = 0; nt < 8; ++nt) {
                int c0 = nt * 8 + 2 * thr;
                float mk0 = msk[c0], mk1 = msk[c0 + 1];
                s[at][nt][0] += mk0;  s[at][nt][1] += mk1;
                s[at][nt][2] += mk0;  s[at][nt][3] += mk1;
                rmax0 = fmaxf(rmax0, fmaxf(s[at][nt][0], s[at][nt][1]));
                rmax1 = fmaxf(rmax1, fmaxf(s[at][nt][2], s[at][nt][3]));
            }
            rmax0 = fmaxf(rmax0, __shfl_xor_sync(0xffffffffu, rmax0, 1));
            rmax0 = fmaxf(rmax0, __shfl_xor_sync(0xffffffffu, rmax0, 2));
            rmax1 = fmaxf(rmax1, __shfl_xor_sync(0xffffffffu, rmax1, 1));
            rmax1 = fmaxf(rmax1, __shfl_xor_sync(0xffffffffu, rmax1, 2));

            const int g0 = at * 2, g1 = at * 2 + 1;
            const float mnew0 = fmaxf(mrun[g0], rmax0);
            const float mnew1 = fmaxf(mrun[g1], rmax1);
            float sum0 = 0.f, sum1 = 0.f;
            #pragma unroll
            for (int nt = 0; nt < 8; ++nt) {
                s[at][nt][0] = __expf(s[at][nt][0] - mnew0);
                s[at][nt][1] = __expf(s[at][nt][1] - mnew0);
                s[at][nt][2] = __expf(s[at][nt][2] - mnew1);
                s[at][nt][3] = __expf(s[at][nt][3] - mnew1);
                sum0 += s[at][nt][0] + s[at][nt][1];
                sum1 += s[at][nt][2] + s[at][nt][3];
            }
            sum0 += __shfl_xor_sync(0xffffffffu, sum0, 1);
            sum0 += __shfl_xor_sync(0xffffffffu, sum0, 2);
            sum1 += __shfl_xor_sync(0xffffffffu, sum1, 1);
            sum1 += __shfl_xor_sync(0xffffffffu, sum1, 2);

            const float cf0 = __expf(mrun[g0] - mnew0);
            const float cf1 = __expf(mrun[g1] - mnew1);
            mrun[g0] = mnew0;  lrun[g0] = lrun[g0] * cf0 + sum0;
            mrun[g1] = mnew1;  lrun[g1] = lrun[g1] * cf1 + sum1;

            #pragma unroll
            for (int nt = 0; nt < 8; ++nt) {
                o[at][nt][0] *= cf0;  o[at][nt][1] *= cf0;
                o[at][nt][2] *= cf1;  o[at][nt][3] *= cf1;
            }

            const int r0 = wr0 + at * 16 + grp;
            #pragma unroll
            for (int nt = 0; nt < 8; ++nt) {
                int c = nt * 8 + 2 * thr;
                uint2 p0 = {f2tf(s[at][nt][0]), f2tf(s[at][nt][1])};
                *reinterpret_cast<uint2*>(&St[r0 * STS_ + c]) = p0;
                uint2 p1 = {f2tf(s[at][nt][2]), f2tf(s[at][nt][3])};
                *reinterpret_cast<uint2*>(&St[(r0 + 8) * STS_ + c]) = p1;
            }
        }
        __syncwarp();

        // ---- O += P @ V : B-frags shared across both A-tiles ----
        #pragma unroll
        for (int kk = 0; kk < 64; kk += 8) {
            uint32_t bfr[8][2];
            #pragma unroll
            for (int nt = 0; nt < 8; ++nt) {
                int d = nt * 8 + grp;
                bfr[nt][0] = Vs[(kk + thr) * VSS + d];
                bfr[nt][1] = Vs[(kk + thr + 4) * VSS + d];
            }
            #pragma unroll
            for (int at = 0; at < 2; ++at) {
                int r0 = wr0 + at * 16 + grp;
                uint32_t a[4];
                a[0] = St[r0 * STS_ + kk + thr];
                a[1] = St[(r0 + 8) * STS_ + kk + thr];
                a[2] = St[r0 * STS_ + kk + thr + 4];
                a[3] = St[(r0 + 8) * STS_ + kk + thr + 4];
                #pragma unroll
                for (int nt = 0; nt < 8; ++nt)
                    MMA_TF32(o[at][nt], a, bfr[nt]);
            }
        }
    }

    // Output: [B, S, H*Dh]
    #pragma unroll
    for (int at = 0; at < 2; ++at) {
        #pragma unroll
        for (int half = 0; half < 2; ++half) {
            const int g = at * 2 + half;
            const float inv = 1.f / lrun[g];
            const int q = q0 + wr0 + at * 16 + grp + half * 8;
            #pragma unroll
            for (int nt = 0; nt < 8; ++nt) {
                int d = nt * 8 + 2 * thr;
                float2 v = {o[at][nt][half * 2 + 0] * inv,
                            o[at][nt][half * 2 + 1] * inv};
                *reinterpret_cast<float2*>(
                    &out[((size_t)(b * S_ + q)) * HID + h * D_ + d]) = v;
            }
        }
    }
}

// ---------------------------------------------------------------------------
// Launch
// ---------------------------------------------------------------------------
extern "C" void kernel_launch(void* const* d_in, const int* in_sizes, int n_in,
                              void* d_out, int out_size)
{
    const float* X    = (const float*)d_in[0];
    const float* mask = (const float*)d_in[1];
    const float* Wq   = (const float*)d_in[2];
    const float* bq   = (const float*)d_in[3];
    const float* Wk   = (const float*)d_in[4];
    const float* bk   = (const float*)d_in[5];
    const float* Wv   = (const float*)d_in[6];
    const float* bv   = (const float*)d_in[7];
    float* out = (float*)d_out;

    float *dQ, *dK, *dV;
    cudaGetSymbolAddress((void**)&dQ, g_Q);
    cudaGetSymbolAddress((void**)&dK, g_K);
    cudaGetSymbolAddress((void**)&dV, g_V);

    const int attn_smem = (128 * QS + 64 * KS + 64 * VSS + 128 * STS_ + 64) * 4;
    cudaFuncSetAttribute(attn_tf32, cudaFuncAttributeMaxDynamicSharedMemorySize, attn_smem);

    dim3 ggrid(HID / 128, M_ / 128, 3);   // (8, 64, 3)
    qkv_gemm3<<<ggrid, 128>>>(X, Wq, Wk, Wv, bq, bk, bv, dQ, dK, dV);

    dim3 agrid(S_ / 128, H_, B_);         // (16, 16, 4)
    attn_tf32<<<agrid, 128, attn_smem>>>(dQ, dK, dV, mask, out);
}

// round 6
// speedup vs baseline: 1.3436x; 1.3436x over previous
#include <cuda_runtime.h>
#include <cuda_bf16.h>
#include <cstdint>

#define B_   4
#define S_   2048
#define H_   16
#define D_   64
#define HID  1024
#define M_   (B_ * S_)

__device__ float g_Q[B_ * H_ * S_ * D_];
__device__ float g_K[B_ * H_ * S_ * D_];
__device__ float g_V[B_ * H_ * S_ * D_];

__device__ __forceinline__ uint32_t f2tf(float x) {
    uint32_t r;
    asm("cvt.rna.tf32.f32 %0, %1;" : "=r"(r) : "f"(x));
    return r;
}
// pack two f32 -> f16x2; lo half = `lo`, hi half = `hi`
__device__ __forceinline__ uint32_t pack_f16x2(float lo, float hi) {
    uint32_t r;
    asm("cvt.rn.f16x2.f32 %0, %1, %2;" : "=r"(r) : "f"(hi), "f"(lo));
    return r;
}

#define MMA_TF32(c, a, b)                                              \
    asm volatile(                                                      \
        "mma.sync.aligned.m16n8k8.row.col.f32.tf32.tf32.f32 "          \
        "{%0,%1,%2,%3}, {%4,%5,%6,%7}, {%8,%9}, {%0,%1,%2,%3};\n"      \
        : "+f"((c)[0]), "+f"((c)[1]), "+f"((c)[2]), "+f"((c)[3])       \
        : "r"((a)[0]), "r"((a)[1]), "r"((a)[2]), "r"((a)[3]),          \
          "r"((b)[0]), "r"((b)[1]))

#define MMA_F16(c, a, b)                                               \
    asm volatile(                                                      \
        "mma.sync.aligned.m16n8k16.row.col.f32.f16.f16.f32 "           \
        "{%0,%1,%2,%3}, {%4,%5,%6,%7}, {%8,%9}, {%0,%1,%2,%3};\n"      \
        : "+f"((c)[0]), "+f"((c)[1]), "+f"((c)[2]), "+f"((c)[3])       \
        : "r"((a)[0]), "r"((a)[1]), "r"((a)[2]), "r"((a)[3]),          \
          "r"((b)[0]), "r"((b)[1]))

// ---------------------------------------------------------------------------
// Kernel A: fused QKV tf32 GEMM, double-buffered.
// 128x128 block, BK=32, 256 threads = 8 warps (2x4), warp tile 64x32.
// Per chunk: LDG (regs) -> compute current buffer -> STS other buffer -> sync.
// ---------------------------------------------------------------------------
#define AS_STRIDE 36   // A-frag bank = 4*grp + thr  -> conflict-free
#define BS_STRIDE 136  // B-frag bank = 8*thr + grp  -> conflict-free
#define A_WORDS  (128 * AS_STRIDE)   // 4608
#define B_WORDS  (32 * BS_STRIDE)    // 4352
#define STAGE_W  (A_WORDS + B_WORDS) // 8960
#define GEMM_SMEM (2 * STAGE_W * 4)  // 71680 B

__global__ __launch_bounds__(256) void qkv_gemm3(const float* __restrict__ X,
                                                 const float* __restrict__ Wq,
                                                 const float* __restrict__ Wk,
                                                 const float* __restrict__ Wv,
                                                 const float* __restrict__ bq,
                                                 const float* __restrict__ bk,
                                                 const float* __restrict__ bv,
                                                 float* __restrict__ oQ,
                                                 float* __restrict__ oK,
                                                 float* __restrict__ oV)
{
    extern __shared__ uint32_t smg[];

    const int z = blockIdx.z;
    const float* W    = (z == 0) ? Wq : (z == 1) ? Wk : Wv;
    const float* bias = (z == 0) ? bq : (z == 1) ? bk : bv;
    float* outh       = (z == 0) ? oQ : (z == 1) ? oK : oV;

    const int tid  = threadIdx.x;
    const int warp = tid >> 5;
    const int lane = tid & 31;
    const int grp  = lane >> 2;
    const int thr  = lane & 3;
    const int wm   = warp >> 2;   // 0..1
    const int wn   = warp & 3;    // 0..3
    const int m0   = blockIdx.y * 128;
    const int n0   = blockIdx.x * 128;

    float acc[4][4][4];
    #pragma unroll
    for (int mt = 0; mt < 4; ++mt)
        #pragma unroll
        for (int nt = 0; nt < 4; ++nt)
            #pragma unroll
            for (int r = 0; r < 4; ++r) acc[mt][nt][r] = 0.f;

    float4 avr[4], bvr[4];
    // prologue: load + store chunk 0
    #pragma unroll
    for (int t = 0; t < 4; ++t) {
        int i  = tid + t * 256;
        int arr = i >> 3, acc4 = (i & 7) * 4;
        avr[t] = *reinterpret_cast<const float4*>(&X[(size_t)(m0 + arr) * HID + acc4]);
        int brr = i >> 5, bcc = (i & 31) * 4;
        bvr[t] = *reinterpret_cast<const float4*>(&W[(size_t)(brr) * HID + n0 + bcc]);
    }
    #pragma unroll
    for (int t = 0; t < 4; ++t) {
        int i  = tid + t * 256;
        int arr = i >> 3, acc4 = (i & 7) * 4;
        uint4 au = {f2tf(avr[t].x), f2tf(avr[t].y), f2tf(avr[t].z), f2tf(avr[t].w)};
        *reinterpret_cast<uint4*>(&smg[arr * AS_STRIDE + acc4]) = au;
        int brr = i >> 5, bcc = (i & 31) * 4;
        uint4 bu = {f2tf(bvr[t].x), f2tf(bvr[t].y), f2tf(bvr[t].z), f2tf(bvr[t].w)};
        *reinterpret_cast<uint4*>(&smg[A_WORDS + brr * BS_STRIDE + bcc]) = bu;
    }
    __syncthreads();

    for (int i = 0; i < 32; ++i) {
        const uint32_t* As = smg + (i & 1) * STAGE_W;
        const uint32_t* Bs = As + A_WORDS;
        // issue next chunk's global loads (latency hidden behind mma block)
        if (i + 1 < 32) {
            const int kn = (i + 1) * 32;
            #pragma unroll
            for (int t = 0; t < 4; ++t) {
                int ii  = tid + t * 256;
                int arr = ii >> 3, acc4 = (ii & 7) * 4;
                avr[t] = *reinterpret_cast<const float4*>(&X[(size_t)(m0 + arr) * HID + kn + acc4]);
                int brr = ii >> 5, bcc = (ii & 31) * 4;
                bvr[t] = *reinterpret_cast<const float4*>(&W[(size_t)(kn + brr) * HID + n0 + bcc]);
            }
        }
        // compute on current buffer
        #pragma unroll
        for (int kk = 0; kk < 32; kk += 8) {
            uint32_t a[4][4], b[4][2];
            #pragma unroll
            for (int mt = 0; mt < 4; ++mt) {
                int r = wm * 64 + mt * 16 + grp;
                a[mt][0] = As[r * AS_STRIDE + kk + thr];
                a[mt][1] = As[(r + 8) * AS_STRIDE + kk + thr];
                a[mt][2] = As[r * AS_STRIDE + kk + thr + 4];
                a[mt][3] = As[(r + 8) * AS_STRIDE + kk + thr + 4];
            }
            #pragma unroll
            for (int nt = 0; nt < 4; ++nt) {
                int c = wn * 32 + nt * 8 + grp;
                b[nt][0] = Bs[(kk + thr) * BS_STRIDE + c];
                b[nt][1] = Bs[(kk + thr + 4) * BS_STRIDE + c];
            }
            #pragma unroll
            for (int mt = 0; mt < 4; ++mt)
                #pragma unroll
                for (int nt = 0; nt < 4; ++nt)
                    MMA_TF32(acc[mt][nt], a[mt], b[nt]);
        }
        // store staged regs into the other buffer
        if (i + 1 < 32) {
            uint32_t* Ad = smg + ((i + 1) & 1) * STAGE_W;
            uint32_t* Bd = Ad + A_WORDS;
            #pragma unroll
            for (int t = 0; t < 4; ++t) {
                int ii  = tid + t * 256;
                int arr = ii >> 3, acc4 = (ii & 7) * 4;
                uint4 au = {f2tf(avr[t].x), f2tf(avr[t].y), f2tf(avr[t].z), f2tf(avr[t].w)};
                *reinterpret_cast<uint4*>(&Ad[arr * AS_STRIDE + acc4]) = au;
                int brr = ii >> 5, bcc = (ii & 31) * 4;
                uint4 bu = {f2tf(bvr[t].x), f2tf(bvr[t].y), f2tf(bvr[t].z), f2tf(bvr[t].w)};
                *reinterpret_cast<uint4*>(&Bd[brr * BS_STRIDE + bcc]) = bu;
            }
        }
        __syncthreads();
    }

    // Epilogue: bias + scatter to [B,H,S,Dh]
    #pragma unroll
    for (int mt = 0; mt < 4; ++mt) {
        #pragma unroll
        for (int nt = 0; nt < 4; ++nt) {
            #pragma unroll
            for (int half = 0; half < 2; ++half) {
                int m = m0 + wm * 64 + mt * 16 + grp + half * 8;
                int bb = m >> 11, s = m & 2047;
                int n = n0 + wn * 32 + nt * 8 + 2 * thr;
                int h = n >> 6, d = n & 63;
                float2 v = {acc[mt][nt][half * 2 + 0] + bias[n],
                            acc[mt][nt][half * 2 + 1] + bias[n + 1]};
                *reinterpret_cast<float2*>(
                    &outh[(((size_t)(bb * H_ + h) * S_) + s) * D_ + d]) = v;
            }
        }
    }
}

// ---------------------------------------------------------------------------
// Kernel B: flash attention. S = QK^T in tf32, P@V in fp16 with P kept in
// registers (C-frag of S == A-frag of m16n8k16 after f16x2 packing).
// Block = (b, h, 128-query tile), 128 threads = 4 warps, Mw=32, Bkv=64.
// ---------------------------------------------------------------------------
#define QS 68     // A-frag bank = 4*grp + thr
#define KS 68     // B-frag bank = 4*grp + thr
#define VP 72     // pair-row stride; bank = 8*thr + grp  (72 mod 32 = 8)

__global__ __launch_bounds__(128) void attn_tf32(const float* __restrict__ Q,
                                                 const float* __restrict__ K,
                                                 const float* __restrict__ V,
                                                 const float* __restrict__ mask,
                                                 float* __restrict__ out)
{
    extern __shared__ uint32_t sm[];
    uint32_t* Qs = sm;                     // [128][QS] tf32, prescaled
    uint32_t* Ks = Qs + 128 * QS;          // [64][KS]  tf32
    uint32_t* Vp = Ks + 64 * KS;           // [32 pairs][VP] f16x2 (keys 2r,2r+1)
    float*   msk = (float*)(Vp + 32 * VP); // [64]

    const int tid  = threadIdx.x;
    const int warp = tid >> 5;
    const int lane = tid & 31;
    const int grp  = lane >> 2;
    const int thr  = lane & 3;
    const int q0   = blockIdx.x * 128;
    const int h    = blockIdx.y;
    const int b    = blockIdx.z;
    const size_t base = (size_t)(b * H_ + h) * S_ * D_;
    const int wr0 = warp * 32;

    // Load Q tile (128 rows), prescale by 1/8 (exact), convert tf32
    #pragma unroll
    for (int t = 0; t < 16; ++t) {
        int i = tid + t * 128;
        int r = i >> 4, c = (i & 15) * 4;
        float4 v = *reinterpret_cast<const float4*>(&Q[base + (size_t)(q0 + r) * D_ + c]);
        uint4 u = {f2tf(v.x * 0.125f), f2tf(v.y * 0.125f),
                   f2tf(v.z * 0.125f), f2tf(v.w * 0.125f)};
        *reinterpret_cast<uint4*>(&Qs[r * QS + c]) = u;
    }

    float mrun[4] = {-1e30f, -1e30f, -1e30f, -1e30f};
    float lrun[4] = {0.f, 0.f, 0.f, 0.f};
    float o[2][8][4];
    #pragma unroll
    for (int at = 0; at < 2; ++at)
        #pragma unroll
        for (int nt = 0; nt < 8; ++nt)
            #pragma unroll
            for (int r = 0; r < 4; ++r) o[at][nt][r] = 0.f;

    for (int k0 = 0; k0 < S_; k0 += 64) {
        __syncthreads();   // prior iter's consumers of Ks/Vp done
        // stage K (tf32) rows
        #pragma unroll
        for (int t = 0; t < 8; ++t) {
            int i = tid + t * 128;
            int r = i >> 4, c = (i & 15) * 4;
            float4 kv = *reinterpret_cast<const float4*>(&K[base + (size_t)(k0 + r) * D_ + c]);
            uint4 ku = {f2tf(kv.x), f2tf(kv.y), f2tf(kv.z), f2tf(kv.w)};
            *reinterpret_cast<uint4*>(&Ks[r * KS + c]) = ku;
        }
        // stage V as f16x2 key-pairs: Vp[kp][d] = {V[2kp][d], V[2kp+1][d]}
        #pragma unroll
        for (int t = 0; t < 4; ++t) {
            int i = tid + t * 128;      // 0..511 : 32 pair-rows x 16 col-quads
            int r2 = i >> 4, c = (i & 15) * 4;
            float4 v0 = *reinterpret_cast<const float4*>(&V[base + (size_t)(k0 + 2 * r2)     * D_ + c]);
            float4 v1 = *reinterpret_cast<const float4*>(&V[base + (size_t)(k0 + 2 * r2 + 1) * D_ + c]);
            uint4 u = {pack_f16x2(v0.x, v1.x), pack_f16x2(v0.y, v1.y),
                       pack_f16x2(v0.z, v1.z), pack_f16x2(v0.w, v1.w)};
            *reinterpret_cast<uint4*>(&Vp[r2 * VP + c]) = u;
        }
        if (tid < 64) msk[tid] = mask[b * S_ + k0 + tid];
        __syncthreads();

        // ---- S = Q @ K^T (tf32) ----
        float s[2][8][4];
        #pragma unroll
        for (int at = 0; at < 2; ++at)
            #pragma unroll
            for (int nt = 0; nt < 8; ++nt)
                #pragma unroll
                for (int r = 0; r < 4; ++r) s[at][nt][r] = 0.f;

        #pragma unroll
        for (int kk = 0; kk < 64; kk += 8) {
            uint32_t bfr[8][2];
            #pragma unroll
            for (int nt = 0; nt < 8; ++nt) {
                int key = nt * 8 + grp;
                bfr[nt][0] = Ks[key * KS + kk + thr];
                bfr[nt][1] = Ks[key * KS + kk + thr + 4];
            }
            #pragma unroll
            for (int at = 0; at < 2; ++at) {
                int r0 = wr0 + at * 16 + grp;
                uint32_t a[4];
                a[0] = Qs[r0 * QS + kk + thr];
                a[1] = Qs[(r0 + 8) * QS + kk + thr];
                a[2] = Qs[r0 * QS + kk + thr + 4];
                a[3] = Qs[(r0 + 8) * QS + kk + thr + 4];
                #pragma unroll
                for (int nt = 0; nt < 8; ++nt)
                    MMA_TF32(s[at][nt], a, bfr[nt]);
            }
        }

        // ---- mask + online softmax; convert P to f16x2 in registers ----
        uint32_t pb[2][8][2];
        #pragma unroll
        for (int at = 0; at < 2; ++at) {
            float rmax0 = -1e30f, rmax1 = -1e30f;
            #pragma unroll
            for (int nt = 0; nt < 8; ++nt) {
                int c0 = nt * 8 + 2 * thr;
                float mk0 = msk[c0], mk1 = msk[c0 + 1];
                s[at][nt][0] += mk0;  s[at][nt][1] += mk1;
                s[at][nt][2] += mk0;  s[at][nt][3] += mk1;
                rmax0 = fmaxf(rmax0, fmaxf(s[at][nt][0], s[at][nt][1]));
                rmax1 = fmaxf(rmax1, fmaxf(s[at][nt][2], s[at][nt][3]));
            }
            rmax0 = fmaxf(rmax0, __shfl_xor_sync(0xffffffffu, rmax0, 1));
            rmax0 = fmaxf(rmax0, __shfl_xor_sync(0xffffffffu, rmax0, 2));
            rmax1 = fmaxf(rmax1, __shfl_xor_sync(0xffffffffu, rmax1, 1));
            rmax1 = fmaxf(rmax1, __shfl_xor_sync(0xffffffffu, rmax1, 2));

            const int g0 = at * 2, g1 = at * 2 + 1;
            const float mnew0 = fmaxf(mrun[g0], rmax0);
            const float mnew1 = fmaxf(mrun[g1], rmax1);
            float sum0 = 0.f, sum1 = 0.f;
            #pragma unroll
            for (int nt = 0; nt < 8; ++nt) {
                s[at][nt][0] = __expf(s[at][nt][0] - mnew0);
                s[at][nt][1] = __expf(s[at][nt][1] - mnew0);
                s[at][nt][2] = __expf(s[at][nt][2] - mnew1);
                s[at][nt][3] = __expf(s[at][nt][3] - mnew1);
                sum0 += s[at][nt][0] + s[at][nt][1];
                sum1 += s[at][nt][2] + s[at][nt][3];
                pb[at][nt][0] = pack_f16x2(s[at][nt][0], s[at][nt][1]);  // row grp
                pb[at][nt][1] = pack_f16x2(s[at][nt][2], s[at][nt][3]);  // row grp+8
            }
            sum0 += __shfl_xor_sync(0xffffffffu, sum0, 1);
            sum0 += __shfl_xor_sync(0xffffffffu, sum0, 2);
            sum1 += __shfl_xor_sync(0xffffffffu, sum1, 1);
            sum1 += __shfl_xor_sync(0xffffffffu, sum1, 2);

            const float cf0 = __expf(mrun[g0] - mnew0);
            const float cf1 = __expf(mrun[g1] - mnew1);
            mrun[g0] = mnew0;  lrun[g0] = lrun[g0] * cf0 + sum0;
            mrun[g1] = mnew1;  lrun[g1] = lrun[g1] * cf1 + sum1;

            #pragma unroll
            for (int nt = 0; nt < 8; ++nt) {
                o[at][nt][0] *= cf0;  o[at][nt][1] *= cf0;
                o[at][nt][2] *= cf1;  o[at][nt][3] *= cf1;
            }
        }

        // ---- O += P @ V (f16 m16n8k16, A from registers) ----
        #pragma unroll
        for (int sstep = 0; sstep < 4; ++sstep) {     // 16 keys per step
            uint32_t bfr[8][2];
            #pragma unroll
            for (int nt = 0; nt < 8; ++nt) {          // d-blocks of 8
                int d = nt * 8 + grp;
                bfr[nt][0] = Vp[(sstep * 8 + thr)     * VP + d];  // keys 2thr,2thr+1
                bfr[nt][1] = Vp[(sstep * 8 + thr + 4) * VP + d];  // keys 8+2thr,8+2thr+1
            }
            #pragma unroll
            for (int at = 0; at < 2; ++at) {
                uint32_t a[4] = {pb[at][2 * sstep][0], pb[at][2 * sstep][1],
                                 pb[at][2 * sstep + 1][0], pb[at][2 * sstep + 1][1]};
                #pragma unroll
                for (int nt = 0; nt < 8; ++nt)
                    MMA_F16(o[at][nt], a, bfr[nt]);
            }
        }
    }

    // Output: [B, S, H*Dh]
    #pragma unroll
    for (int at = 0; at < 2; ++at) {
        #pragma unroll
        for (int half = 0; half < 2; ++half) {
            const int g = at * 2 + half;
            const float inv = 1.f / lrun[g];
            const int q = q0 + wr0 + at * 16 + grp + half * 8;
            #pragma unroll
            for (int nt = 0; nt < 8; ++nt) {
                int d = nt * 8 + 2 * thr;
                float2 v = {o[at][nt][half * 2 + 0] * inv,
                            o[at][nt][half * 2 + 1] * inv};
                *reinterpret_cast<float2*>(
                    &out[((size_t)(b * S_ + q)) * HID + h * D_ + d]) = v;
            }
        }
    }
}

// ---------------------------------------------------------------------------
// Launch
// ---------------------------------------------------------------------------
extern "C" void kernel_launch(void* const* d_in, const int* in_sizes, int n_in,
                              void* d_out, int out_size)
{
    const float* X    = (const float*)d_in[0];
    const float* mask = (const float*)d_in[1];
    const float* Wq   = (const float*)d_in[2];
    const float* bq   = (const float*)d_in[3];
    const float* Wk   = (const float*)d_in[4];
    const float* bk   = (const float*)d_in[5];
    const float* Wv   = (const float*)d_in[6];
    const float* bv   = (const float*)d_in[7];
    float* out = (float*)d_out;

    float *dQ, *dK, *dV;
    cudaGetSymbolAddress((void**)&dQ, g_Q);
    cudaGetSymbolAddress((void**)&dK, g_K);
    cudaGetSymbolAddress((void**)&dV, g_V);

    cudaFuncSetAttribute(qkv_gemm3, cudaFuncAttributeMaxDynamicSharedMemorySize, GEMM_SMEM);
    const int attn_smem = (128 * QS + 64 * KS + 32 * VP + 64) * 4;   // ~61.7 KB
    cudaFuncSetAttribute(attn_tf32, cudaFuncAttributeMaxDynamicSharedMemorySize, attn_smem);

    dim3 ggrid(HID / 128, M_ / 128, 3);   // (8, 64, 3)
    qkv_gemm3<<<ggrid, 256, GEMM_SMEM>>>(X, Wq, Wk, Wv, bq, bk, bv, dQ, dK, dV);

    dim3 agrid(S_ / 128, H_, B_);         // (16, 16, 4)
    attn_tf32<<<agrid, 128, attn_smem>>>(dQ, dK, dV, mask, out);
}

// round 7
// speedup vs baseline: 1.4317x; 1.0656x over previous
#include <cuda_runtime.h>
#include <cuda_bf16.h>
#include <cstdint>

#define B_   4
#define S_   2048
#define H_   16
#define D_   64
#define HID  1024
#define M_   (B_ * S_)

__device__ float g_Q[B_ * H_ * S_ * D_];
__device__ float g_K[B_ * H_ * S_ * D_];
__device__ float g_V[B_ * H_ * S_ * D_];

__device__ __forceinline__ uint32_t f2tf(float x) {
    uint32_t r;
    asm("cvt.rna.tf32.f32 %0, %1;" : "=r"(r) : "f"(x));
    return r;
}
__device__ __forceinline__ uint32_t pack_f16x2(float lo, float hi) {
    uint32_t r;
    asm("cvt.rn.f16x2.f32 %0, %1, %2;" : "=r"(r) : "f"(hi), "f"(lo));
    return r;
}
__device__ __forceinline__ uint32_t smem_u32(const void* p) {
    uint32_t a;
    asm("{ .reg .u64 t; cvta.to.shared.u64 t, %1; cvt.u32.u64 %0, t; }" : "=r"(a) : "l"(p));
    return a;
}
__device__ __forceinline__ void cp16(uint32_t saddr, const void* gptr) {
    asm volatile("cp.async.ca.shared.global [%0], [%1], 16;" :: "r"(saddr), "l"(gptr));
}
#define CP_COMMIT() asm volatile("cp.async.commit_group;" ::: "memory")
#define CP_WAIT0()  asm volatile("cp.async.wait_group 0;" ::: "memory")

#define MMA_TF32(c, a, b)                                              \
    asm volatile(                                                      \
        "mma.sync.aligned.m16n8k8.row.col.f32.tf32.tf32.f32 "          \
        "{%0,%1,%2,%3}, {%4,%5,%6,%7}, {%8,%9}, {%0,%1,%2,%3};\n"      \
        : "+f"((c)[0]), "+f"((c)[1]), "+f"((c)[2]), "+f"((c)[3])       \
        : "r"((a)[0]), "r"((a)[1]), "r"((a)[2]), "r"((a)[3]),          \
          "r"((b)[0]), "r"((b)[1]))

#define MMA_F16(c, a, b)                                               \
    asm volatile(                                                      \
        "mma.sync.aligned.m16n8k16.row.col.f32.f16.f16.f32 "           \
        "{%0,%1,%2,%3}, {%4,%5,%6,%7}, {%8,%9}, {%0,%1,%2,%3};\n"      \
        : "+f"((c)[0]), "+f"((c)[1]), "+f"((c)[2]), "+f"((c)[3])       \
        : "r"((a)[0]), "r"((a)[1]), "r"((a)[2]), "r"((a)[3]),          \
          "r"((b)[0]), "r"((b)[1]))

// ---------------------------------------------------------------------------
// Kernel A: fused QKV tf32 GEMM, double-buffered (unchanged from R6).
// ---------------------------------------------------------------------------
#define AS_STRIDE 36
#define BS_STRIDE 136
#define A_WORDS  (128 * AS_STRIDE)
#define B_WORDS  (32 * BS_STRIDE)
#define STAGE_W  (A_WORDS + B_WORDS)
#define GEMM_SMEM (2 * STAGE_W * 4)

__global__ __launch_bounds__(256) void qkv_gemm3(const float* __restrict__ X,
                                                 const float* __restrict__ Wq,
                                                 const float* __restrict__ Wk,
                                                 const float* __restrict__ Wv,
                                                 const float* __restrict__ bq,
                                                 const float* __restrict__ bk,
                                                 const float* __restrict__ bv,
                                                 float* __restrict__ oQ,
                                                 float* __restrict__ oK,
                                                 float* __restrict__ oV)
{
    extern __shared__ uint32_t smg[];

    const int z = blockIdx.z;
    const float* W    = (z == 0) ? Wq : (z == 1) ? Wk : Wv;
    const float* bias = (z == 0) ? bq : (z == 1) ? bk : bv;
    float* outh       = (z == 0) ? oQ : (z == 1) ? oK : oV;

    const int tid  = threadIdx.x;
    const int warp = tid >> 5;
    const int lane = tid & 31;
    const int grp  = lane >> 2;
    const int thr  = lane & 3;
    const int wm   = warp >> 2;
    const int wn   = warp & 3;
    const int m0   = blockIdx.y * 128;
    const int n0   = blockIdx.x * 128;

    float acc[4][4][4];
    #pragma unroll
    for (int mt = 0; mt < 4; ++mt)
        #pragma unroll
        for (int nt = 0; nt < 4; ++nt)
            #pragma unroll
            for (int r = 0; r < 4; ++r) acc[mt][nt][r] = 0.f;

    float4 avr[4], bvr[4];
    #pragma unroll
    for (int t = 0; t < 4; ++t) {
        int i  = tid + t * 256;
        int arr = i >> 3, acc4 = (i & 7) * 4;
        avr[t] = *reinterpret_cast<const float4*>(&X[(size_t)(m0 + arr) * HID + acc4]);
        int brr = i >> 5, bcc = (i & 31) * 4;
        bvr[t] = *reinterpret_cast<const float4*>(&W[(size_t)(brr) * HID + n0 + bcc]);
    }
    #pragma unroll
    for (int t = 0; t < 4; ++t) {
        int i  = tid + t * 256;
        int arr = i >> 3, acc4 = (i & 7) * 4;
        uint4 au = {f2tf(avr[t].x), f2tf(avr[t].y), f2tf(avr[t].z), f2tf(avr[t].w)};
        *reinterpret_cast<uint4*>(&smg[arr * AS_STRIDE + acc4]) = au;
        int brr = i >> 5, bcc = (i & 31) * 4;
        uint4 bu = {f2tf(bvr[t].x), f2tf(bvr[t].y), f2tf(bvr[t].z), f2tf(bvr[t].w)};
        *reinterpret_cast<uint4*>(&smg[A_WORDS + brr * BS_STRIDE + bcc]) = bu;
    }
    __syncthreads();

    for (int i = 0; i < 32; ++i) {
        const uint32_t* As = smg + (i & 1) * STAGE_W;
        const uint32_t* Bs = As + A_WORDS;
        if (i + 1 < 32) {
            const int kn = (i + 1) * 32;
            #pragma unroll
            for (int t = 0; t < 4; ++t) {
                int ii  = tid + t * 256;
                int arr = ii >> 3, acc4 = (ii & 7) * 4;
                avr[t] = *reinterpret_cast<const float4*>(&X[(size_t)(m0 + arr) * HID + kn + acc4]);
                int brr = ii >> 5, bcc = (ii & 31) * 4;
                bvr[t] = *reinterpret_cast<const float4*>(&W[(size_t)(kn + brr) * HID + n0 + bcc]);
            }
        }
        #pragma unroll
        for (int kk = 0; kk < 32; kk += 8) {
            uint32_t a[4][4], b[4][2];
            #pragma unroll
            for (int mt = 0; mt < 4; ++mt) {
                int r = wm * 64 + mt * 16 + grp;
                a[mt][0] = As[r * AS_STRIDE + kk + thr];
                a[mt][1] = As[(r + 8) * AS_STRIDE + kk + thr];
                a[mt][2] = As[r * AS_STRIDE + kk + thr + 4];
                a[mt][3] = As[(r + 8) * AS_STRIDE + kk + thr + 4];
            }
            #pragma unroll
            for (int nt = 0; nt < 4; ++nt) {
                int c = wn * 32 + nt * 8 + grp;
                b[nt][0] = Bs[(kk + thr) * BS_STRIDE + c];
                b[nt][1] = Bs[(kk + thr + 4) * BS_STRIDE + c];
            }
            #pragma unroll
            for (int mt = 0; mt < 4; ++mt)
                #pragma unroll
                for (int nt = 0; nt < 4; ++nt)
                    MMA_TF32(acc[mt][nt], a[mt], b[nt]);
        }
        if (i + 1 < 32) {
            uint32_t* Ad = smg + ((i + 1) & 1) * STAGE_W;
            uint32_t* Bd = Ad + A_WORDS;
            #pragma unroll
            for (int t = 0; t < 4; ++t) {
                int ii  = tid + t * 256;
                int arr = ii >> 3, acc4 = (ii & 7) * 4;
                uint4 au = {f2tf(avr[t].x), f2tf(avr[t].y), f2tf(avr[t].z), f2tf(avr[t].w)};
                *reinterpret_cast<uint4*>(&Ad[arr * AS_STRIDE + acc4]) = au;
                int brr = ii >> 5, bcc = (ii & 31) * 4;
                uint4 bu = {f2tf(bvr[t].x), f2tf(bvr[t].y), f2tf(bvr[t].z), f2tf(bvr[t].w)};
                *reinterpret_cast<uint4*>(&Bd[brr * BS_STRIDE + bcc]) = bu;
            }
        }
        __syncthreads();
    }

    #pragma unroll
    for (int mt = 0; mt < 4; ++mt) {
        #pragma unroll
        for (int nt = 0; nt < 4; ++nt) {
            #pragma unroll
            for (int half = 0; half < 2; ++half) {
                int m = m0 + wm * 64 + mt * 16 + grp + half * 8;
                int bb = m >> 11, s = m & 2047;
                int n = n0 + wn * 32 + nt * 8 + 2 * thr;
                int h = n >> 6, d = n & 63;
                float2 v = {acc[mt][nt][half * 2 + 0] + bias[n],
                            acc[mt][nt][half * 2 + 1] + bias[n + 1]};
                *reinterpret_cast<float2*>(
                    &outh[(((size_t)(bb * H_ + h) * S_) + s) * D_ + d]) = v;
            }
        }
    }
}

// ---------------------------------------------------------------------------
// Kernel B: flash attention, software-pipelined KV staging.
// K via cp.async (raw f32 read as tf32), V prefetched to regs -> f16x2,
// mask via cp.async. Double-buffered; ONE __syncthreads per KV tile.
// ---------------------------------------------------------------------------
#define QS 68
#define KS 68
#define VP 72
#define QW   (128 * QS)          // 8704 words
#define KW   (64 * KS)           // 4352 words per buffer
#define VW   (32 * VP)           // 2304 words per buffer
#define OFF_K0  QW
#define OFF_K1  (QW + KW)
#define OFF_V0  (QW + 2 * KW)
#define OFF_V1  (QW + 2 * KW + VW)
#define OFF_M0  (QW + 2 * KW + 2 * VW)
#define OFF_M1  (OFF_M0 + 64)
#define ATTN_WORDS (OFF_M1 + 64)           // 22144 words = 88576 B

__global__ __launch_bounds__(128) void attn_tf32(const float* __restrict__ Q,
                                                 const float* __restrict__ K,
                                                 const float* __restrict__ V,
                                                 const float* __restrict__ mask,
                                                 float* __restrict__ out)
{
    extern __shared__ uint32_t sm[];
    const uint32_t sbase = smem_u32(sm);

    const int tid  = threadIdx.x;
    const int warp = tid >> 5;
    const int lane = tid & 31;
    const int grp  = lane >> 2;
    const int thr  = lane & 3;
    const int q0   = blockIdx.x * 128;
    const int h    = blockIdx.y;
    const int b    = blockIdx.z;
    const size_t base = (size_t)(b * H_ + h) * S_ * D_;
    const int wr0 = warp * 32;

    // K cp.async coordinates (64 rows x 16 granules, 8 per thread)
    const int kr = tid >> 4;            // stepping by 8 rows per t
    const int kc4 = (tid & 15) * 4;

    // ---- prologue: Q staging + issue tile-0 loads ----
    #pragma unroll
    for (int t = 0; t < 16; ++t) {
        int i = tid + t * 128;
        int r = i >> 4, c = (i & 15) * 4;
        float4 v = *reinterpret_cast<const float4*>(&Q[base + (size_t)(q0 + r) * D_ + c]);
        uint4 u = {f2tf(v.x * 0.125f), f2tf(v.y * 0.125f),
                   f2tf(v.z * 0.125f), f2tf(v.w * 0.125f)};
        *reinterpret_cast<uint4*>(&sm[r * QS + c]) = u;
    }
    #pragma unroll
    for (int t = 0; t < 8; ++t) {
        int r = kr + t * 8;
        cp16(sbase + (OFF_K0 + r * KS + kc4) * 4, &K[base + (size_t)r * D_ + kc4]);
    }
    if (tid < 16) cp16(sbase + (OFF_M0 + tid * 4) * 4, &mask[b * S_ + tid * 4]);
    CP_COMMIT();

    float4 vr[8];
    #pragma unroll
    for (int t = 0; t < 4; ++t) {
        int i = tid + t * 128;
        int r2 = i >> 4, c = (i & 15) * 4;
        vr[2 * t]     = *reinterpret_cast<const float4*>(&V[base + (size_t)(2 * r2)     * D_ + c]);
        vr[2 * t + 1] = *reinterpret_cast<const float4*>(&V[base + (size_t)(2 * r2 + 1) * D_ + c]);
    }

    float mrun[4] = {-1e30f, -1e30f, -1e30f, -1e30f};
    float lrun[4] = {0.f, 0.f, 0.f, 0.f};
    float o[2][8][4];
    #pragma unroll
    for (int at = 0; at < 2; ++at)
        #pragma unroll
        for (int nt = 0; nt < 8; ++nt)
            #pragma unroll
            for (int r = 0; r < 4; ++r) o[at][nt][r] = 0.f;

    for (int it = 0; it < 32; ++it) {
        const int bu = it & 1;
        const uint32_t* Ks = sm + (bu ? OFF_K1 : OFF_K0);
        const uint32_t* Vp = sm + (bu ? OFF_V1 : OFF_V0);
        const float*   msk = (const float*)(sm + (bu ? OFF_M1 : OFF_M0));
        uint32_t* Vd = sm + (bu ? OFF_V1 : OFF_V0);

        // stage V(it) from prefetched regs (f16x2 key pairs)
        #pragma unroll
        for (int t = 0; t < 4; ++t) {
            int i = tid + t * 128;
            int r2 = i >> 4, c = (i & 15) * 4;
            float4 v0 = vr[2 * t], v1 = vr[2 * t + 1];
            uint4 u = {pack_f16x2(v0.x, v1.x), pack_f16x2(v0.y, v1.y),
                       pack_f16x2(v0.z, v1.z), pack_f16x2(v0.w, v1.w)};
            *reinterpret_cast<uint4*>(&Vd[r2 * VP + c]) = u;
        }
        CP_WAIT0();
        __syncthreads();   // tile `it` staging visible; buffers of it-1 free

        // issue loads for tile it+1 (latency hidden behind compute)
        if (it + 1 < 32) {
            const int kn = (it + 1) * 64;
            const uint32_t koff = bu ? OFF_K0 : OFF_K1;   // other buffer
            #pragma unroll
            for (int t = 0; t < 8; ++t) {
                int r = kr + t * 8;
                cp16(sbase + (koff + r * KS + kc4) * 4,
                     &K[base + (size_t)(kn + r) * D_ + kc4]);
            }
            if (tid < 16)
                cp16(sbase + ((bu ? OFF_M0 : OFF_M1) + tid * 4) * 4,
                     &mask[b * S_ + kn + tid * 4]);
            CP_COMMIT();
            #pragma unroll
            for (int t = 0; t < 4; ++t) {
                int i = tid + t * 128;
                int r2 = i >> 4, c = (i & 15) * 4;
                vr[2 * t]     = *reinterpret_cast<const float4*>(&V[base + (size_t)(kn + 2 * r2)     * D_ + c]);
                vr[2 * t + 1] = *reinterpret_cast<const float4*>(&V[base + (size_t)(kn + 2 * r2 + 1) * D_ + c]);
            }
        }

        // ---- S = Q @ K^T (tf32; K raw f32 bits, HW truncates) ----
        float s[2][8][4];
        #pragma unroll
        for (int at = 0; at < 2; ++at)
            #pragma unroll
            for (int nt = 0; nt < 8; ++nt)
                #pragma unroll
                for (int r = 0; r < 4; ++r) s[at][nt][r] = 0.f;

        #pragma unroll
        for (int kk = 0; kk < 64; kk += 8) {
            uint32_t bfr[8][2];
            #pragma unroll
            for (int nt = 0; nt < 8; ++nt) {
                int key = nt * 8 + grp;
                bfr[nt][0] = Ks[key * KS + kk + thr];
                bfr[nt][1] = Ks[key * KS + kk + thr + 4];
            }
            #pragma unroll
            for (int at = 0; at < 2; ++at) {
                int r0 = wr0 + at * 16 + grp;
                uint32_t a[4];
                a[0] = sm[r0 * QS + kk + thr];
                a[1] = sm[(r0 + 8) * QS + kk + thr];
                a[2] = sm[r0 * QS + kk + thr + 4];
                a[3] = sm[(r0 + 8) * QS + kk + thr + 4];
                #pragma unroll
                for (int nt = 0; nt < 8; ++nt)
                    MMA_TF32(s[at][nt], a, bfr[nt]);
            }
        }

        // ---- mask + online softmax; P -> f16x2 in registers ----
        uint32_t pb[2][8][2];
        #pragma unroll
        for (int at = 0; at < 2; ++at) {
            float rmax0 = -1e30f, rmax1 = -1e30f;
            #pragma unroll
            for (int nt = 0; nt < 8; ++nt) {
                int c0 = nt * 8 + 2 * thr;
                float mk0 = msk[c0], mk1 = msk[c0 + 1];
                s[at][nt][0] += mk0;  s[at][nt][1] += mk1;
                s[at][nt][2] += mk0;  s[at][nt][3] += mk1;
                rmax0 = fmaxf(rmax0, fmaxf(s[at][nt][0], s[at][nt][1]));
                rmax1 = fmaxf(rmax1, fmaxf(s[at][nt][2], s[at][nt][3]));
            }
            rmax0 = fmaxf(rmax0, __shfl_xor_sync(0xffffffffu, rmax0, 1));
            rmax0 = fmaxf(rmax0, __shfl_xor_sync(0xffffffffu, rmax0, 2));
            rmax1 = fmaxf(rmax1, __shfl_xor_sync(0xffffffffu, rmax1, 1));
            rmax1 = fmaxf(rmax1, __shfl_xor_sync(0xffffffffu, rmax1, 2));

            const int g0 = at * 2, g1 = at * 2 + 1;
            const float mnew0 = fmaxf(mrun[g0], rmax0);
            const float mnew1 = fmaxf(mrun[g1], rmax1);
            float sum0 = 0.f, sum1 = 0.f;
            #pragma unroll
            for (int nt = 0; nt < 8; ++nt) {
                s[at][nt][0] = __expf(s[at][nt][0] - mnew0);
                s[at][nt][1] = __expf(s[at][nt][1] - mnew0);
                s[at][nt][2] = __expf(s[at][nt][2] - mnew1);
                s[at][nt][3] = __expf(s[at][nt][3] - mnew1);
                sum0 += s[at][nt][0] + s[at][nt][1];
                sum1 += s[at][nt][2] + s[at][nt][3];
                pb[at][nt][0] = pack_f16x2(s[at][nt][0], s[at][nt][1]);
                pb[at][nt][1] = pack_f16x2(s[at][nt][2], s[at][nt][3]);
            }
            sum0 += __shfl_xor_sync(0xffffffffu, sum0, 1);
            sum0 += __shfl_xor_sync(0xffffffffu, sum0, 2);
            sum1 += __shfl_xor_sync(0xffffffffu, sum1, 1);
            sum1 += __shfl_xor_sync(0xffffffffu, sum1, 2);

            const float cf0 = __expf(mrun[g0] - mnew0);
            const float cf1 = __expf(mrun[g1] - mnew1);
            mrun[g0] = mnew0;  lrun[g0] = lrun[g0] * cf0 + sum0;
            mrun[g1] = mnew1;  lrun[g1] = lrun[g1] * cf1 + sum1;

            #pragma unroll
            for (int nt = 0; nt < 8; ++nt) {
                o[at][nt][0] *= cf0;  o[at][nt][1] *= cf0;
                o[at][nt][2] *= cf1;  o[at][nt][3] *= cf1;
            }
        }

        // ---- O += P @ V (f16 m16n8k16, A from registers) ----
        #pragma unroll
        for (int sstep = 0; sstep < 4; ++sstep) {
            uint32_t bfr[8][2];
            #pragma unroll
            for (int nt = 0; nt < 8; ++nt) {
                int d = nt * 8 + grp;
                bfr[nt][0] = Vp[(sstep * 8 + thr)     * VP + d];
                bfr[nt][1] = Vp[(sstep * 8 + thr + 4) * VP + d];
            }
            #pragma unroll
            for (int at = 0; at < 2; ++at) {
                uint32_t a[4] = {pb[at][2 * sstep][0], pb[at][2 * sstep][1],
                                 pb[at][2 * sstep + 1][0], pb[at][2 * sstep + 1][1]};
                #pragma unroll
                for (int nt = 0; nt < 8; ++nt)
                    MMA_F16(o[at][nt], a, bfr[nt]);
            }
        }
        __syncthreads();   // compute(it) done before next iter's staging writes
    }

    // Output: [B, S, H*Dh]
    #pragma unroll
    for (int at = 0; at < 2; ++at) {
        #pragma unroll
        for (int half = 0; half < 2; ++half) {
            const int g = at * 2 + half;
            const float inv = 1.f / lrun[g];
            const int q = q0 + wr0 + at * 16 + grp + half * 8;
            #pragma unroll
            for (int nt = 0; nt < 8; ++nt) {
                int d = nt * 8 + 2 * thr;
                float2 v = {o[at][nt][half * 2 + 0] * inv,
                            o[at][nt][half * 2 + 1] * inv};
                *reinterpret_cast<float2*>(
                    &out[((size_t)(b * S_ + q)) * HID + h * D_ + d]) = v;
            }
        }
    }
}

// ---------------------------------------------------------------------------
// Launch
// ---------------------------------------------------------------------------
extern "C" void kernel_launch(void* const* d_in, const int* in_sizes, int n_in,
                              void* d_out, int out_size)
{
    const float* X    = (const float*)d_in[0];
    const float* mask = (const float*)d_in[1];
    const float* Wq   = (const float*)d_in[2];
    const float* bq   = (const float*)d_in[3];
    const float* Wk   = (const float*)d_in[4];
    const float* bk   = (const float*)d_in[5];
    const float* Wv   = (const float*)d_in[6];
    const float* bv   = (const float*)d_in[7];
    float* out = (float*)d_out;

    float *dQ, *dK, *dV;
    cudaGetSymbolAddress((void**)&dQ, g_Q);
    cudaGetSymbolAddress((void**)&dK, g_K);
    cudaGetSymbolAddress((void**)&dV, g_V);

    cudaFuncSetAttribute(qkv_gemm3, cudaFuncAttributeMaxDynamicSharedMemorySize, GEMM_SMEM);
    const int attn_smem = ATTN_WORDS * 4;   // 88576 B
    cudaFuncSetAttribute(attn_tf32, cudaFuncAttributeMaxDynamicSharedMemorySize, attn_smem);

    dim3 ggrid(HID / 128, M_ / 128, 3);   // (8, 64, 3)
    qkv_gemm3<<<ggrid, 256, GEMM_SMEM>>>(X, Wq, Wk, Wv, bq, bk, bv, dQ, dK, dV);

    dim3 agrid(S_ / 128, H_, B_);         // (16, 16, 4)
    attn_tf32<<<agrid, 128, attn_smem>>>(dQ, dK, dV, mask, out);
}

// round 8
// speedup vs baseline: 1.7788x; 1.2424x over previous
#include <cuda_runtime.h>
#include <cuda_bf16.h>
#include <cstdint>

#define B_   4
#define S_   2048
#define H_   16
#define D_   64
#define HID  1024
#define M_   (B_ * S_)

__device__ float g_Q[B_ * H_ * S_ * D_];
__device__ float g_K[B_ * H_ * S_ * D_];
__device__ float g_V[B_ * H_ * S_ * D_];

__device__ __forceinline__ uint32_t f2tf(float x) {
    uint32_t r;
    asm("cvt.rna.tf32.f32 %0, %1;" : "=r"(r) : "f"(x));
    return r;
}
__device__ __forceinline__ uint32_t pack_f16x2(float lo, float hi) {
    uint32_t r;
    asm("cvt.rn.f16x2.f32 %0, %1, %2;" : "=r"(r) : "f"(hi), "f"(lo));
    return r;
}
__device__ __forceinline__ uint32_t smem_u32(const void* p) {
    uint32_t a;
    asm("{ .reg .u64 t; cvta.to.shared.u64 t, %1; cvt.u32.u64 %0, t; }" : "=r"(a) : "l"(p));
    return a;
}
__device__ __forceinline__ void cp16(uint32_t saddr, const void* gptr) {
    asm volatile("cp.async.ca.shared.global [%0], [%1], 16;" :: "r"(saddr), "l"(gptr));
}
#define CP_COMMIT() asm volatile("cp.async.commit_group;" ::: "memory")
#define CP_WAIT0()  asm volatile("cp.async.wait_group 0;" ::: "memory")

#define MMA_TF32(c, a, b)                                              \
    asm volatile(                                                      \
        "mma.sync.aligned.m16n8k8.row.col.f32.tf32.tf32.f32 "          \
        "{%0,%1,%2,%3}, {%4,%5,%6,%7}, {%8,%9}, {%0,%1,%2,%3};\n"      \
        : "+f"((c)[0]), "+f"((c)[1]), "+f"((c)[2]), "+f"((c)[3])       \
        : "r"((a)[0]), "r"((a)[1]), "r"((a)[2]), "r"((a)[3]),          \
          "r"((b)[0]), "r"((b)[1]))

#define MMA_F16(c, a, b)                                               \
    asm volatile(                                                      \
        "mma.sync.aligned.m16n8k16.row.col.f32.f16.f16.f32 "           \
        "{%0,%1,%2,%3}, {%4,%5,%6,%7}, {%8,%9}, {%0,%1,%2,%3};\n"      \
        : "+f"((c)[0]), "+f"((c)[1]), "+f"((c)[2]), "+f"((c)[3])       \
        : "r"((a)[0]), "r"((a)[1]), "r"((a)[2]), "r"((a)[3]),          \
          "r"((b)[0]), "r"((b)[1]))

// ---------------------------------------------------------------------------
// Kernel A: fused QKV GEMM in fp16 (m16n8k16), double-buffered.
// 128x128 block, BK=32 (2 k16 steps), 256 threads = 8 warps (2x4), warp 64x32.
// A: Ah[row][kpair] stride 20 (frag bank = 20*grp+thr, conflict-free).
// B: Bp[kpair][n]  stride 136 (frag bank = 8*thr+grp, conflict-free; STS.128).
// ---------------------------------------------------------------------------
#define AH_S 20
#define BP_S 136
#define AH_W (128 * AH_S)            // 2560 words / buffer
#define BP_W (16 * BP_S)             // 2176 words / buffer
#define STG_W (AH_W + BP_W)          // 4736
#define GEMM_SMEM (2 * STG_W * 4)    // 37888 B

__global__ __launch_bounds__(256) void qkv_gemm3(const float* __restrict__ X,
                                                 const float* __restrict__ Wq,
                                                 const float* __restrict__ Wk,
                                                 const float* __restrict__ Wv,
                                                 const float* __restrict__ bq,
                                                 const float* __restrict__ bk,
                                                 const float* __restrict__ bv,
                                                 float* __restrict__ oQ,
                                                 float* __restrict__ oK,
                                                 float* __restrict__ oV)
{
    extern __shared__ uint32_t smg[];

    const int z = blockIdx.z;
    const float* W    = (z == 0) ? Wq : (z == 1) ? Wk : Wv;
    const float* bias = (z == 0) ? bq : (z == 1) ? bk : bv;
    float* outh       = (z == 0) ? oQ : (z == 1) ? oK : oV;

    const int tid  = threadIdx.x;
    const int warp = tid >> 5;
    const int lane = tid & 31;
    const int grp  = lane >> 2;
    const int thr  = lane & 3;
    const int wm   = warp >> 2;
    const int wn   = warp & 3;
    const int m0   = blockIdx.y * 128;
    const int n0   = blockIdx.x * 128;

    // A staging coords: i = tid + t*256, t<4 : row = i>>3, q = i&7 (k = 4q)
    // B staging coords: i = tid + t*256, t<2 : kp = i>>5, n4 = (i&31)*4
    float acc[4][4][4];
    #pragma unroll
    for (int mt = 0; mt < 4; ++mt)
        #pragma unroll
        for (int nt = 0; nt < 4; ++nt)
            #pragma unroll
            for (int r = 0; r < 4; ++r) acc[mt][nt][r] = 0.f;

    float4 avr[4], b0r[2], b1r[2];
    // prologue: load chunk 0
    #pragma unroll
    for (int t = 0; t < 4; ++t) {
        int i = tid + t * 256;
        int row = i >> 3, q = i & 7;
        avr[t] = *reinterpret_cast<const float4*>(&X[(size_t)(m0 + row) * HID + q * 4]);
    }
    #pragma unroll
    for (int t = 0; t < 2; ++t) {
        int i = tid + t * 256;
        int kp = i >> 5, n4 = (i & 31) * 4;
        b0r[t] = *reinterpret_cast<const float4*>(&W[(size_t)(2 * kp)     * HID + n0 + n4]);
        b1r[t] = *reinterpret_cast<const float4*>(&W[(size_t)(2 * kp + 1) * HID + n0 + n4]);
    }
    // store chunk 0
    #pragma unroll
    for (int t = 0; t < 4; ++t) {
        int i = tid + t * 256;
        int row = i >> 3, q = i & 7;
        uint2 u = {pack_f16x2(avr[t].x, avr[t].y), pack_f16x2(avr[t].z, avr[t].w)};
        *reinterpret_cast<uint2*>(&smg[row * AH_S + 2 * q]) = u;
    }
    #pragma unroll
    for (int t = 0; t < 2; ++t) {
        int i = tid + t * 256;
        int kp = i >> 5, n4 = (i & 31) * 4;
        uint4 u = {pack_f16x2(b0r[t].x, b1r[t].x), pack_f16x2(b0r[t].y, b1r[t].y),
                   pack_f16x2(b0r[t].z, b1r[t].z), pack_f16x2(b0r[t].w, b1r[t].w)};
        *reinterpret_cast<uint4*>(&smg[AH_W + kp * BP_S + n4]) = u;
    }
    __syncthreads();

    for (int i = 0; i < 32; ++i) {
        const uint32_t* Ah = smg + (i & 1) * STG_W;
        const uint32_t* Bp = Ah + AH_W;
        // issue next chunk's global loads
        if (i + 1 < 32) {
            const int kn = (i + 1) * 32;
            #pragma unroll
            for (int t = 0; t < 4; ++t) {
                int ii = tid + t * 256;
                int row = ii >> 3, q = ii & 7;
                avr[t] = *reinterpret_cast<const float4*>(&X[(size_t)(m0 + row) * HID + kn + q * 4]);
            }
            #pragma unroll
            for (int t = 0; t < 2; ++t) {
                int ii = tid + t * 256;
                int kp = ii >> 5, n4 = (ii & 31) * 4;
                b0r[t] = *reinterpret_cast<const float4*>(&W[(size_t)(kn + 2 * kp)     * HID + n0 + n4]);
                b1r[t] = *reinterpret_cast<const float4*>(&W[(size_t)(kn + 2 * kp + 1) * HID + n0 + n4]);
            }
        }
        // compute current buffer: 2 k16 steps
        #pragma unroll
        for (int s = 0; s < 2; ++s) {
            uint32_t a[4][4], b[4][2];
            #pragma unroll
            for (int mt = 0; mt < 4; ++mt) {
                int r = wm * 64 + mt * 16 + grp;
                a[mt][0] = Ah[r * AH_S + s * 8 + thr];
                a[mt][1] = Ah[(r + 8) * AH_S + s * 8 + thr];
                a[mt][2] = Ah[r * AH_S + s * 8 + 4 + thr];
                a[mt][3] = Ah[(r + 8) * AH_S + s * 8 + 4 + thr];
            }
            #pragma unroll
            for (int nt = 0; nt < 4; ++nt) {
                int c = wn * 32 + nt * 8 + grp;
                b[nt][0] = Bp[(s * 8 + thr)     * BP_S + c];
                b[nt][1] = Bp[(s * 8 + thr + 4) * BP_S + c];
            }
            #pragma unroll
            for (int mt = 0; mt < 4; ++mt)
                #pragma unroll
                for (int nt = 0; nt < 4; ++nt)
                    MMA_F16(acc[mt][nt], a[mt], b[nt]);
        }
        // store staged regs into the other buffer
        if (i + 1 < 32) {
            uint32_t* Ad = smg + ((i + 1) & 1) * STG_W;
            uint32_t* Bd = Ad + AH_W;
            #pragma unroll
            for (int t = 0; t < 4; ++t) {
                int ii = tid + t * 256;
                int row = ii >> 3, q = ii & 7;
                uint2 u = {pack_f16x2(avr[t].x, avr[t].y), pack_f16x2(avr[t].z, avr[t].w)};
                *reinterpret_cast<uint2*>(&Ad[row * AH_S + 2 * q]) = u;
            }
            #pragma unroll
            for (int t = 0; t < 2; ++t) {
                int ii = tid + t * 256;
                int kp = ii >> 5, n4 = (ii & 31) * 4;
                uint4 u = {pack_f16x2(b0r[t].x, b1r[t].x), pack_f16x2(b0r[t].y, b1r[t].y),
                           pack_f16x2(b0r[t].z, b1r[t].z), pack_f16x2(b0r[t].w, b1r[t].w)};
                *reinterpret_cast<uint4*>(&Bd[kp * BP_S + n4]) = u;
            }
        }
        __syncthreads();
    }

    // Epilogue: bias + scatter to [B,H,S,Dh]
    #pragma unroll
    for (int mt = 0; mt < 4; ++mt) {
        #pragma unroll
        for (int nt = 0; nt < 4; ++nt) {
            #pragma unroll
            for (int half = 0; half < 2; ++half) {
                int m = m0 + wm * 64 + mt * 16 + grp + half * 8;
                int bb = m >> 11, s = m & 2047;
                int n = n0 + wn * 32 + nt * 8 + 2 * thr;
                int h = n >> 6, d = n & 63;
                float2 v = {acc[mt][nt][half * 2 + 0] + bias[n],
                            acc[mt][nt][half * 2 + 1] + bias[n + 1]};
                *reinterpret_cast<float2*>(
                    &outh[(((size_t)(bb * H_ + h) * S_) + s) * D_ + d]) = v;
            }
        }
    }
}

// ---------------------------------------------------------------------------
// Kernel B: flash attention (unchanged from R7): pipelined cp.async K (tf32),
// reg-prefetched V -> f16x2, P in registers, one __syncthreads per tile.
// ---------------------------------------------------------------------------
#define QS 68
#define KS 68
#define VP 72
#define QW   (128 * QS)
#define KW   (64 * KS)
#define VW   (32 * VP)
#define OFF_K0  QW
#define OFF_K1  (QW + KW)
#define OFF_V0  (QW + 2 * KW)
#define OFF_V1  (QW + 2 * KW + VW)
#define OFF_M0  (QW + 2 * KW + 2 * VW)
#define OFF_M1  (OFF_M0 + 64)
#define ATTN_WORDS (OFF_M1 + 64)

__global__ __launch_bounds__(128) void attn_tf32(const float* __restrict__ Q,
                                                 const float* __restrict__ K,
                                                 const float* __restrict__ V,
                                                 const float* __restrict__ mask,
                                                 float* __restrict__ out)
{
    extern __shared__ uint32_t sm[];
    const uint32_t sbase = smem_u32(sm);

    const int tid  = threadIdx.x;
    const int warp = tid >> 5;
    const int lane = tid & 31;
    const int grp  = lane >> 2;
    const int thr  = lane & 3;
    const int q0   = blockIdx.x * 128;
    const int h    = blockIdx.y;
    const int b    = blockIdx.z;
    const size_t base = (size_t)(b * H_ + h) * S_ * D_;
    const int wr0 = warp * 32;

    const int kr = tid >> 4;
    const int kc4 = (tid & 15) * 4;

    #pragma unroll
    for (int t = 0; t < 16; ++t) {
        int i = tid + t * 128;
        int r = i >> 4, c = (i & 15) * 4;
        float4 v = *reinterpret_cast<const float4*>(&Q[base + (size_t)(q0 + r) * D_ + c]);
        uint4 u = {f2tf(v.x * 0.125f), f2tf(v.y * 0.125f),
                   f2tf(v.z * 0.125f), f2tf(v.w * 0.125f)};
        *reinterpret_cast<uint4*>(&sm[r * QS + c]) = u;
    }
    #pragma unroll
    for (int t = 0; t < 8; ++t) {
        int r = kr + t * 8;
        cp16(sbase + (OFF_K0 + r * KS + kc4) * 4, &K[base + (size_t)r * D_ + kc4]);
    }
    if (tid < 16) cp16(sbase + (OFF_M0 + tid * 4) * 4, &mask[b * S_ + tid * 4]);
    CP_COMMIT();

    float4 vr[8];
    #pragma unroll
    for (int t = 0; t < 4; ++t) {
        int i = tid + t * 128;
        int r2 = i >> 4, c = (i & 15) * 4;
        vr[2 * t]     = *reinterpret_cast<const float4*>(&V[base + (size_t)(2 * r2)     * D_ + c]);
        vr[2 * t + 1] = *reinterpret_cast<const float4*>(&V[base + (size_t)(2 * r2 + 1) * D_ + c]);
    }

    float mrun[4] = {-1e30f, -1e30f, -1e30f, -1e30f};
    float lrun[4] = {0.f, 0.f, 0.f, 0.f};
    float o[2][8][4];
    #pragma unroll
    for (int at = 0; at < 2; ++at)
        #pragma unroll
        for (int nt = 0; nt < 8; ++nt)
            #pragma unroll
            for (int r = 0; r < 4; ++r) o[at][nt][r] = 0.f;

    for (int it = 0; it < 32; ++it) {
        const int bu = it & 1;
        const uint32_t* Ks = sm + (bu ? OFF_K1 : OFF_K0);
        const uint32_t* Vp = sm + (bu ? OFF_V1 : OFF_V0);
        const float*   msk = (const float*)(sm + (bu ? OFF_M1 : OFF_M0));
        uint32_t* Vd = sm + (bu ? OFF_V1 : OFF_V0);

        #pragma unroll
        for (int t = 0; t < 4; ++t) {
            int i = tid + t * 128;
            int r2 = i >> 4, c = (i & 15) * 4;
            float4 v0 = vr[2 * t], v1 = vr[2 * t + 1];
            uint4 u = {pack_f16x2(v0.x, v1.x), pack_f16x2(v0.y, v1.y),
                       pack_f16x2(v0.z, v1.z), pack_f16x2(v0.w, v1.w)};
            *reinterpret_cast<uint4*>(&Vd[r2 * VP + c]) = u;
        }
        CP_WAIT0();
        __syncthreads();

        if (it + 1 < 32) {
            const int kn = (it + 1) * 64;
            const uint32_t koff = bu ? OFF_K0 : OFF_K1;
            #pragma unroll
            for (int t = 0; t < 8; ++t) {
                int r = kr + t * 8;
                cp16(sbase + (koff + r * KS + kc4) * 4,
                     &K[base + (size_t)(kn + r) * D_ + kc4]);
            }
            if (tid < 16)
                cp16(sbase + ((bu ? OFF_M0 : OFF_M1) + tid * 4) * 4,
                     &mask[b * S_ + kn + tid * 4]);
            CP_COMMIT();
            #pragma unroll
            for (int t = 0; t < 4; ++t) {
                int i = tid + t * 128;
                int r2 = i >> 4, c = (i & 15) * 4;
                vr[2 * t]     = *reinterpret_cast<const float4*>(&V[base + (size_t)(kn + 2 * r2)     * D_ + c]);
                vr[2 * t + 1] = *reinterpret_cast<const float4*>(&V[base + (size_t)(kn + 2 * r2 + 1) * D_ + c]);
            }
        }

        float s[2][8][4];
        #pragma unroll
        for (int at = 0; at < 2; ++at)
            #pragma unroll
            for (int nt = 0; nt < 8; ++nt)
                #pragma unroll
                for (int r = 0; r < 4; ++r) s[at][nt][r] = 0.f;

        #pragma unroll
        for (int kk = 0; kk < 64; kk += 8) {
            uint32_t bfr[8][2];
            #pragma unroll
            for (int nt = 0; nt < 8; ++nt) {
                int key = nt * 8 + grp;
                bfr[nt][0] = Ks[key * KS + kk + thr];
                bfr[nt][1] = Ks[key * KS + kk + thr + 4];
            }
            #pragma unroll
            for (int at = 0; at < 2; ++at) {
                int r0 = wr0 + at * 16 + grp;
                uint32_t a[4];
                a[0] = sm[r0 * QS + kk + thr];
                a[1] = sm[(r0 + 8) * QS + kk + thr];
                a[2] = sm[r0 * QS + kk + thr + 4];
                a[3] = sm[(r0 + 8) * QS + kk + thr + 4];
                #pragma unroll
                for (int nt = 0; nt < 8; ++nt)
                    MMA_TF32(s[at][nt], a, bfr[nt]);
            }
        }

        uint32_t pb[2][8][2];
        #pragma unroll
        for (int at = 0; at < 2; ++at) {
            float rmax0 = -1e30f, rmax1 = -1e30f;
            #pragma unroll
            for (int nt = 0; nt < 8; ++nt) {
                int c0 = nt * 8 + 2 * thr;
                float mk0 = msk[c0], mk1 = msk[c0 + 1];
                s[at][nt][0] += mk0;  s[at][nt][1] += mk1;
                s[at][nt][2] += mk0;  s[at][nt][3] += mk1;
                rmax0 = fmaxf(rmax0, fmaxf(s[at][nt][0], s[at][nt][1]));
                rmax1 = fmaxf(rmax1, fmaxf(s[at][nt][2], s[at][nt][3]));
            }
            rmax0 = fmaxf(rmax0, __shfl_xor_sync(0xffffffffu, rmax0, 1));
            rmax0 = fmaxf(rmax0, __shfl_xor_sync(0xffffffffu, rmax0, 2));
            rmax1 = fmaxf(rmax1, __shfl_xor_sync(0xffffffffu, rmax1, 1));
            rmax1 = fmaxf(rmax1, __shfl_xor_sync(0xffffffffu, rmax1, 2));

            const int g0 = at * 2, g1 = at * 2 + 1;
            const float mnew0 = fmaxf(mrun[g0], rmax0);
            const float mnew1 = fmaxf(mrun[g1], rmax1);
            float sum0 = 0.f, sum1 = 0.f;
            #pragma unroll
            for (int nt = 0; nt < 8; ++nt) {
                s[at][nt][0] = __expf(s[at][nt][0] - mnew0);
                s[at][nt][1] = __expf(s[at][nt][1] - mnew0);
                s[at][nt][2] = __expf(s[at][nt][2] - mnew1);
                s[at][nt][3] = __expf(s[at][nt][3] - mnew1);
                sum0 += s[at][nt][0] + s[at][nt][1];
                sum1 += s[at][nt][2] + s[at][nt][3];
                pb[at][nt][0] = pack_f16x2(s[at][nt][0], s[at][nt][1]);
                pb[at][nt][1] = pack_f16x2(s[at][nt][2], s[at][nt][3]);
            }
            sum0 += __shfl_xor_sync(0xffffffffu, sum0, 1);
            sum0 += __shfl_xor_sync(0xffffffffu, sum0, 2);
            sum1 += __shfl_xor_sync(0xffffffffu, sum1, 1);
            sum1 += __shfl_xor_sync(0xffffffffu, sum1, 2);

            const float cf0 = __expf(mrun[g0] - mnew0);
            const float cf1 = __expf(mrun[g1] - mnew1);
            mrun[g0] = mnew0;  lrun[g0] = lrun[g0] * cf0 + sum0;
            mrun[g1] = mnew1;  lrun[g1] = lrun[g1] * cf1 + sum1;

            #pragma unroll
            for (int nt = 0; nt < 8; ++nt) {
                o[at][nt][0] *= cf0;  o[at][nt][1] *= cf0;
                o[at][nt][2] *= cf1;  o[at][nt][3] *= cf1;
            }
        }

        #pragma unroll
        for (int sstep = 0; sstep < 4; ++sstep) {
            uint32_t bfr[8][2];
            #pragma unroll
            for (int nt = 0; nt < 8; ++nt) {
                int d = nt * 8 + grp;
                bfr[nt][0] = Vp[(sstep * 8 + thr)     * VP + d];
                bfr[nt][1] = Vp[(sstep * 8 + thr + 4) * VP + d];
            }
            #pragma unroll
            for (int at = 0; at < 2; ++at) {
                uint32_t a[4] = {pb[at][2 * sstep][0], pb[at][2 * sstep][1],
                                 pb[at][2 * sstep + 1][0], pb[at][2 * sstep + 1][1]};
                #pragma unroll
                for (int nt = 0; nt < 8; ++nt)
                    MMA_F16(o[at][nt], a, bfr[nt]);
            }
        }
        __syncthreads();
    }

    #pragma unroll
    for (int at = 0; at < 2; ++at) {
        #pragma unroll
        for (int half = 0; half < 2; ++half) {
            const int g = at * 2 + half;
            const float inv = 1.f / lrun[g];
            const int q = q0 + wr0 + at * 16 + grp + half * 8;
            #pragma unroll
            for (int nt = 0; nt < 8; ++nt) {
                int d = nt * 8 + 2 * thr;
                float2 v = {o[at][nt][half * 2 + 0] * inv,
                            o[at][nt][half * 2 + 1] * inv};
                *reinterpret_cast<float2*>(
                    &out[((size_t)(b * S_ + q)) * HID + h * D_ + d]) = v;
            }
        }
    }
}

// ---------------------------------------------------------------------------
// Launch
// ---------------------------------------------------------------------------
extern "C" void kernel_launch(void* const* d_in, const int* in_sizes, int n_in,
                              void* d_out, int out_size)
{
    const float* X    = (const float*)d_in[0];
    const float* mask = (const float*)d_in[1];
    const float* Wq   = (const float*)d_in[2];
    const float* bq   = (const float*)d_in[3];
    const float* Wk   = (const float*)d_in[4];
    const float* bk   = (const float*)d_in[5];
    const float* Wv   = (const float*)d_in[6];
    const float* bv   = (const float*)d_in[7];
    float* out = (float*)d_out;

    float *dQ, *dK, *dV;
    cudaGetSymbolAddress((void**)&dQ, g_Q);
    cudaGetSymbolAddress((void**)&dK, g_K);
    cudaGetSymbolAddress((void**)&dV, g_V);

    cudaFuncSetAttribute(qkv_gemm3, cudaFuncAttributeMaxDynamicSharedMemorySize, GEMM_SMEM);
    const int attn_smem = ATTN_WORDS * 4;
    cudaFuncSetAttribute(attn_tf32, cudaFuncAttributeMaxDynamicSharedMemorySize, attn_smem);

    dim3 ggrid(HID / 128, M_ / 128, 3);   // (8, 64, 3)
    qkv_gemm3<<<ggrid, 256, GEMM_SMEM>>>(X, Wq, Wk, Wv, bq, bk, bv, dQ, dK, dV);

    dim3 agrid(S_ / 128, H_, B_);         // (16, 16, 4)
    attn_tf32<<<agrid, 128, attn_smem>>>(dQ, dK, dV, mask, out);
}

// round 9
// speedup vs baseline: 2.1195x; 1.1915x over previous
#include <cuda_runtime.h>
#include <cuda_bf16.h>
#include <cstdint>

#define B_   4
#define S_   2048
#define H_   16
#define D_   64
#define HID  1024
#define M_   (B_ * S_)

__device__ float g_Q[B_ * H_ * S_ * D_];
__device__ float g_K[B_ * H_ * S_ * D_];
__device__ float g_V[B_ * H_ * S_ * D_];

__device__ __forceinline__ uint32_t pack_f16x2(float lo, float hi) {
    uint32_t r;
    asm("cvt.rn.f16x2.f32 %0, %1, %2;" : "=r"(r) : "f"(hi), "f"(lo));
    return r;
}
__device__ __forceinline__ uint32_t smem_u32(const void* p) {
    uint32_t a;
    asm("{ .reg .u64 t; cvta.to.shared.u64 t, %1; cvt.u32.u64 %0, t; }" : "=r"(a) : "l"(p));
    return a;
}
__device__ __forceinline__ void cp16(uint32_t saddr, const void* gptr) {
    asm volatile("cp.async.ca.shared.global [%0], [%1], 16;" :: "r"(saddr), "l"(gptr));
}
#define CP_COMMIT() asm volatile("cp.async.commit_group;" ::: "memory")
#define CP_WAIT0()  asm volatile("cp.async.wait_group 0;" ::: "memory")

#define MMA_F16(c, a, b)                                               \
    asm volatile(                                                      \
        "mma.sync.aligned.m16n8k16.row.col.f32.f16.f16.f32 "           \
        "{%0,%1,%2,%3}, {%4,%5,%6,%7}, {%8,%9}, {%0,%1,%2,%3};\n"      \
        : "+f"((c)[0]), "+f"((c)[1]), "+f"((c)[2]), "+f"((c)[3])       \
        : "r"((a)[0]), "r"((a)[1]), "r"((a)[2]), "r"((a)[3]),          \
          "r"((b)[0]), "r"((b)[1]))

// ---------------------------------------------------------------------------
// Kernel A: fused QKV GEMM in fp16 (unchanged from R8).
// ---------------------------------------------------------------------------
#define AH_S 20
#define BP_S 136
#define AH_W (128 * AH_S)
#define BP_W (16 * BP_S)
#define STG_W (AH_W + BP_W)
#define GEMM_SMEM (2 * STG_W * 4)

__global__ __launch_bounds__(256) void qkv_gemm3(const float* __restrict__ X,
                                                 const float* __restrict__ Wq,
                                                 const float* __restrict__ Wk,
                                                 const float* __restrict__ Wv,
                                                 const float* __restrict__ bq,
                                                 const float* __restrict__ bk,
                                                 const float* __restrict__ bv,
                                                 float* __restrict__ oQ,
                                                 float* __restrict__ oK,
                                                 float* __restrict__ oV)
{
    extern __shared__ uint32_t smg[];

    const int z = blockIdx.z;
    const float* W    = (z == 0) ? Wq : (z == 1) ? Wk : Wv;
    const float* bias = (z == 0) ? bq : (z == 1) ? bk : bv;
    float* outh       = (z == 0) ? oQ : (z == 1) ? oK : oV;

    const int tid  = threadIdx.x;
    const int warp = tid >> 5;
    const int lane = tid & 31;
    const int grp  = lane >> 2;
    const int thr  = lane & 3;
    const int wm   = warp >> 2;
    const int wn   = warp & 3;
    const int m0   = blockIdx.y * 128;
    const int n0   = blockIdx.x * 128;

    float acc[4][4][4];
    #pragma unroll
    for (int mt = 0; mt < 4; ++mt)
        #pragma unroll
        for (int nt = 0; nt < 4; ++nt)
            #pragma unroll
            for (int r = 0; r < 4; ++r) acc[mt][nt][r] = 0.f;

    float4 avr[4], b0r[2], b1r[2];
    #pragma unroll
    for (int t = 0; t < 4; ++t) {
        int i = tid + t * 256;
        int row = i >> 3, q = i & 7;
        avr[t] = *reinterpret_cast<const float4*>(&X[(size_t)(m0 + row) * HID + q * 4]);
    }
    #pragma unroll
    for (int t = 0; t < 2; ++t) {
        int i = tid + t * 256;
        int kp = i >> 5, n4 = (i & 31) * 4;
        b0r[t] = *reinterpret_cast<const float4*>(&W[(size_t)(2 * kp)     * HID + n0 + n4]);
        b1r[t] = *reinterpret_cast<const float4*>(&W[(size_t)(2 * kp + 1) * HID + n0 + n4]);
    }
    #pragma unroll
    for (int t = 0; t < 4; ++t) {
        int i = tid + t * 256;
        int row = i >> 3, q = i & 7;
        uint2 u = {pack_f16x2(avr[t].x, avr[t].y), pack_f16x2(avr[t].z, avr[t].w)};
        *reinterpret_cast<uint2*>(&smg[row * AH_S + 2 * q]) = u;
    }
    #pragma unroll
    for (int t = 0; t < 2; ++t) {
        int i = tid + t * 256;
        int kp = i >> 5, n4 = (i & 31) * 4;
        uint4 u = {pack_f16x2(b0r[t].x, b1r[t].x), pack_f16x2(b0r[t].y, b1r[t].y),
                   pack_f16x2(b0r[t].z, b1r[t].z), pack_f16x2(b0r[t].w, b1r[t].w)};
        *reinterpret_cast<uint4*>(&smg[AH_W + kp * BP_S + n4]) = u;
    }
    __syncthreads();

    for (int i = 0; i < 32; ++i) {
        const uint32_t* Ah = smg + (i & 1) * STG_W;
        const uint32_t* Bp = Ah + AH_W;
        if (i + 1 < 32) {
            const int kn = (i + 1) * 32;
            #pragma unroll
            for (int t = 0; t < 4; ++t) {
                int ii = tid + t * 256;
                int row = ii >> 3, q = ii & 7;
                avr[t] = *reinterpret_cast<const float4*>(&X[(size_t)(m0 + row) * HID + kn + q * 4]);
            }
            #pragma unroll
            for (int t = 0; t < 2; ++t) {
                int ii = tid + t * 256;
                int kp = ii >> 5, n4 = (ii & 31) * 4;
                b0r[t] = *reinterpret_cast<const float4*>(&W[(size_t)(kn + 2 * kp)     * HID + n0 + n4]);
                b1r[t] = *reinterpret_cast<const float4*>(&W[(size_t)(kn + 2 * kp + 1) * HID + n0 + n4]);
            }
        }
        #pragma unroll
        for (int s = 0; s < 2; ++s) {
            uint32_t a[4][4], b[4][2];
            #pragma unroll
            for (int mt = 0; mt < 4; ++mt) {
                int r = wm * 64 + mt * 16 + grp;
                a[mt][0] = Ah[r * AH_S + s * 8 + thr];
                a[mt][1] = Ah[(r + 8) * AH_S + s * 8 + thr];
                a[mt][2] = Ah[r * AH_S + s * 8 + 4 + thr];
                a[mt][3] = Ah[(r + 8) * AH_S + s * 8 + 4 + thr];
            }
            #pragma unroll
            for (int nt = 0; nt < 4; ++nt) {
                int c = wn * 32 + nt * 8 + grp;
                b[nt][0] = Bp[(s * 8 + thr)     * BP_S + c];
                b[nt][1] = Bp[(s * 8 + thr + 4) * BP_S + c];
            }
            #pragma unroll
            for (int mt = 0; mt < 4; ++mt)
                #pragma unroll
                for (int nt = 0; nt < 4; ++nt)
                    MMA_F16(acc[mt][nt], a[mt], b[nt]);
        }
        if (i + 1 < 32) {
            uint32_t* Ad = smg + ((i + 1) & 1) * STG_W;
            uint32_t* Bd = Ad + AH_W;
            #pragma unroll
            for (int t = 0; t < 4; ++t) {
                int ii = tid + t * 256;
                int row = ii >> 3, q = ii & 7;
                uint2 u = {pack_f16x2(avr[t].x, avr[t].y), pack_f16x2(avr[t].z, avr[t].w)};
                *reinterpret_cast<uint2*>(&Ad[row * AH_S + 2 * q]) = u;
            }
            #pragma unroll
            for (int t = 0; t < 2; ++t) {
                int ii = tid + t * 256;
                int kp = ii >> 5, n4 = (ii & 31) * 4;
                uint4 u = {pack_f16x2(b0r[t].x, b1r[t].x), pack_f16x2(b0r[t].y, b1r[t].y),
                           pack_f16x2(b0r[t].z, b1r[t].z), pack_f16x2(b0r[t].w, b1r[t].w)};
                *reinterpret_cast<uint4*>(&Bd[kp * BP_S + n4]) = u;
            }
        }
        __syncthreads();
    }

    #pragma unroll
    for (int mt = 0; mt < 4; ++mt) {
        #pragma unroll
        for (int nt = 0; nt < 4; ++nt) {
            #pragma unroll
            for (int half = 0; half < 2; ++half) {
                int m = m0 + wm * 64 + mt * 16 + grp + half * 8;
                int bb = m >> 11, s = m & 2047;
                int n = n0 + wn * 32 + nt * 8 + 2 * thr;
                int h = n >> 6, d = n & 63;
                float2 v = {acc[mt][nt][half * 2 + 0] + bias[n],
                            acc[mt][nt][half * 2 + 1] + bias[n + 1]};
                *reinterpret_cast<float2*>(
                    &outh[(((size_t)(bb * H_ + h) * S_) + s) * D_ + d]) = v;
            }
        }
    }
}

// ---------------------------------------------------------------------------
// Kernel B: flash attention, all-fp16 mma (k16 for both QK^T and PV).
// Q fp16 pair-major; K cp.async raw f32 (double buf) -> per-tile smem convert
// to Kp[key][dpair]; V reg-prefetch -> f16x2 (single buf); P in registers.
// smem 70.5KB -> 3 blocks/SM.
// ---------------------------------------------------------------------------
#define QH 36     // Q: [128 rows][32 dpairs]+pad, A-frag bank 4*grp+thr
#define KR 68     // K raw f32: [64 keys][64 d]+pad
#define KP 36     // K packed: [64 keys][32 dpairs]+pad, B-frag bank 4*grp+thr
#define VP 72     // V packed: [32 kpairs][64 d]+pad, B-frag bank 8*thr+grp
#define QW2     (128 * QH)                 // 4608
#define OFF_KR0 QW2                        // 4608
#define OFF_KR1 (QW2 + 64 * KR)            // 8960
#define OFF_KP  (OFF_KR1 + 64 * KR)        // 13312
#define OFF_V   (OFF_KP + 64 * KP)         // 15616
#define OFF_M0  (OFF_V + 32 * VP)          // 17920
#define OFF_M1  (OFF_M0 + 64)
#define ATTN_WORDS (OFF_M1 + 64)           // 18048 words = 72192 B

__global__ __launch_bounds__(128) void attn_f16(const float* __restrict__ Q,
                                                const float* __restrict__ K,
                                                const float* __restrict__ V,
                                                const float* __restrict__ mask,
                                                float* __restrict__ out)
{
    extern __shared__ uint32_t sm[];
    const uint32_t sbase = smem_u32(sm);

    const int tid  = threadIdx.x;
    const int warp = tid >> 5;
    const int lane = tid & 31;
    const int grp  = lane >> 2;
    const int thr  = lane & 3;
    const int q0   = blockIdx.x * 128;
    const int h    = blockIdx.y;
    const int b    = blockIdx.z;
    const size_t base = (size_t)(b * H_ + h) * S_ * D_;
    const int wr0 = warp * 32;

    const int kr  = tid >> 4;
    const int kc4 = (tid & 15) * 4;

    // ---- prologue: Q -> fp16 pair-major (prescaled by 1/8), K tile0 cp.async ----
    #pragma unroll
    for (int t = 0; t < 16; ++t) {
        int i = tid + t * 128;
        int r = i >> 4, c = (i & 15) * 4;
        float4 v = *reinterpret_cast<const float4*>(&Q[base + (size_t)(q0 + r) * D_ + c]);
        uint2 u = {pack_f16x2(v.x * 0.125f, v.y * 0.125f),
                   pack_f16x2(v.z * 0.125f, v.w * 0.125f)};
        *reinterpret_cast<uint2*>(&sm[r * QH + (c >> 1)]) = u;
    }
    #pragma unroll
    for (int t = 0; t < 8; ++t) {
        int r = kr + t * 8;
        cp16(sbase + (OFF_KR0 + r * KR + kc4) * 4, &K[base + (size_t)r * D_ + kc4]);
    }
    if (tid < 16) cp16(sbase + (OFF_M0 + tid * 4) * 4, &mask[b * S_ + tid * 4]);
    CP_COMMIT();

    float4 vr[8];
    #pragma unroll
    for (int t = 0; t < 4; ++t) {
        int i = tid + t * 128;
        int r2 = i >> 4, c = (i & 15) * 4;
        vr[2 * t]     = *reinterpret_cast<const float4*>(&V[base + (size_t)(2 * r2)     * D_ + c]);
        vr[2 * t + 1] = *reinterpret_cast<const float4*>(&V[base + (size_t)(2 * r2 + 1) * D_ + c]);
    }

    float mrun[4] = {-1e30f, -1e30f, -1e30f, -1e30f};
    float lrun[4] = {0.f, 0.f, 0.f, 0.f};
    float o[2][8][4];
    #pragma unroll
    for (int at = 0; at < 2; ++at)
        #pragma unroll
        for (int nt = 0; nt < 8; ++nt)
            #pragma unroll
            for (int r = 0; r < 4; ++r) o[at][nt][r] = 0.f;

    for (int it = 0; it < 32; ++it) {
        const int bu = it & 1;
        const float* Kraw = (const float*)(sm + (bu ? OFF_KR1 : OFF_KR0));
        const float* msk  = (const float*)(sm + (bu ? OFF_M1 : OFF_M0));

        CP_WAIT0();
        __syncthreads();   // Kraw(it) visible; all compute of it-1 done (V/Kp free)

        // stage V(it) from prefetched regs (single buffer)
        #pragma unroll
        for (int t = 0; t < 4; ++t) {
            int i = tid + t * 128;
            int r2 = i >> 4, c = (i & 15) * 4;
            float4 v0 = vr[2 * t], v1 = vr[2 * t + 1];
            uint4 u = {pack_f16x2(v0.x, v1.x), pack_f16x2(v0.y, v1.y),
                       pack_f16x2(v0.z, v1.z), pack_f16x2(v0.w, v1.w)};
            *reinterpret_cast<uint4*>(&sm[OFF_V + r2 * VP + c]) = u;
        }
        // convert K raw f32 -> fp16 pair-major Kp[key][dpair]
        #pragma unroll
        for (int t = 0; t < 8; ++t) {
            int i = tid + t * 128;
            int key = i >> 4, c = (i & 15) * 4;
            float4 kv = *reinterpret_cast<const float4*>(&Kraw[key * KR + c]);
            uint2 u = {pack_f16x2(kv.x, kv.y), pack_f16x2(kv.z, kv.w)};
            *reinterpret_cast<uint2*>(&sm[OFF_KP + key * KP + (c >> 1)]) = u;
        }
        // issue loads for tile it+1
        if (it + 1 < 32) {
            const int kn = (it + 1) * 64;
            const uint32_t koff = bu ? OFF_KR0 : OFF_KR1;
            #pragma unroll
            for (int t = 0; t < 8; ++t) {
                int r = kr + t * 8;
                cp16(sbase + (koff + r * KR + kc4) * 4,
                     &K[base + (size_t)(kn + r) * D_ + kc4]);
            }
            if (tid < 16)
                cp16(sbase + ((bu ? OFF_M0 : OFF_M1) + tid * 4) * 4,
                     &mask[b * S_ + kn + tid * 4]);
            CP_COMMIT();
            #pragma unroll
            for (int t = 0; t < 4; ++t) {
                int i = tid + t * 128;
                int r2 = i >> 4, c = (i & 15) * 4;
                vr[2 * t]     = *reinterpret_cast<const float4*>(&V[base + (size_t)(kn + 2 * r2)     * D_ + c]);
                vr[2 * t + 1] = *reinterpret_cast<const float4*>(&V[base + (size_t)(kn + 2 * r2 + 1) * D_ + c]);
            }
        }
        __syncthreads();   // V + Kp staged

        // ---- S = Q @ K^T (fp16 k16) ----
        float s[2][8][4];
        #pragma unroll
        for (int at = 0; at < 2; ++at)
            #pragma unroll
            for (int nt = 0; nt < 8; ++nt)
                #pragma unroll
                for (int r = 0; r < 4; ++r) s[at][nt][r] = 0.f;

        #pragma unroll
        for (int ks = 0; ks < 4; ++ks) {         // dpairs ks*8 .. ks*8+7
            uint32_t bfr[8][2];
            #pragma unroll
            for (int nt = 0; nt < 8; ++nt) {
                int key = nt * 8 + grp;
                bfr[nt][0] = sm[OFF_KP + key * KP + ks * 8 + thr];
                bfr[nt][1] = sm[OFF_KP + key * KP + ks * 8 + 4 + thr];
            }
            #pragma unroll
            for (int at = 0; at < 2; ++at) {
                int r0 = wr0 + at * 16 + grp;
                uint32_t a[4];
                a[0] = sm[r0 * QH + ks * 8 + thr];
                a[1] = sm[(r0 + 8) * QH + ks * 8 + thr];
                a[2] = sm[r0 * QH + ks * 8 + 4 + thr];
                a[3] = sm[(r0 + 8) * QH + ks * 8 + 4 + thr];
                #pragma unroll
                for (int nt = 0; nt < 8; ++nt)
                    MMA_F16(s[at][nt], a, bfr[nt]);
            }
        }

        // ---- mask + online softmax; P -> f16x2 in registers ----
        uint32_t pb[2][8][2];
        #pragma unroll
        for (int at = 0; at < 2; ++at) {
            float rmax0 = -1e30f, rmax1 = -1e30f;
            #pragma unroll
            for (int nt = 0; nt < 8; ++nt) {
                int c0 = nt * 8 + 2 * thr;
                float mk0 = msk[c0], mk1 = msk[c0 + 1];
                s[at][nt][0] += mk0;  s[at][nt][1] += mk1;
                s[at][nt][2] += mk0;  s[at][nt][3] += mk1;
                rmax0 = fmaxf(rmax0, fmaxf(s[at][nt][0], s[at][nt][1]));
                rmax1 = fmaxf(rmax1, fmaxf(s[at][nt][2], s[at][nt][3]));
            }
            rmax0 = fmaxf(rmax0, __shfl_xor_sync(0xffffffffu, rmax0, 1));
            rmax0 = fmaxf(rmax0, __shfl_xor_sync(0xffffffffu, rmax0, 2));
            rmax1 = fmaxf(rmax1, __shfl_xor_sync(0xffffffffu, rmax1, 1));
            rmax1 = fmaxf(rmax1, __shfl_xor_sync(0xffffffffu, rmax1, 2));

            const int g0 = at * 2, g1 = at * 2 + 1;
            const float mnew0 = fmaxf(mrun[g0], rmax0);
            const float mnew1 = fmaxf(mrun[g1], rmax1);
            float sum0 = 0.f, sum1 = 0.f;
            #pragma unroll
            for (int nt = 0; nt < 8; ++nt) {
                s[at][nt][0] = __expf(s[at][nt][0] - mnew0);
                s[at][nt][1] = __expf(s[at][nt][1] - mnew0);
                s[at][nt][2] = __expf(s[at][nt][2] - mnew1);
                s[at][nt][3] = __expf(s[at][nt][3] - mnew1);
                sum0 += s[at][nt][0] + s[at][nt][1];
                sum1 += s[at][nt][2] + s[at][nt][3];
                pb[at][nt][0] = pack_f16x2(s[at][nt][0], s[at][nt][1]);
                pb[at][nt][1] = pack_f16x2(s[at][nt][2], s[at][nt][3]);
            }
            sum0 += __shfl_xor_sync(0xffffffffu, sum0, 1);
            sum0 += __shfl_xor_sync(0xffffffffu, sum0, 2);
            sum1 += __shfl_xor_sync(0xffffffffu, sum1, 1);
            sum1 += __shfl_xor_sync(0xffffffffu, sum1, 2);

            const float cf0 = __expf(mrun[g0] - mnew0);
            const float cf1 = __expf(mrun[g1] - mnew1);
            mrun[g0] = mnew0;  lrun[g0] = lrun[g0] * cf0 + sum0;
            mrun[g1] = mnew1;  lrun[g1] = lrun[g1] * cf1 + sum1;

            #pragma unroll
            for (int nt = 0; nt < 8; ++nt) {
                o[at][nt][0] *= cf0;  o[at][nt][1] *= cf0;
                o[at][nt][2] *= cf1;  o[at][nt][3] *= cf1;
            }
        }

        // ---- O += P @ V (fp16 k16, A from registers) ----
        #pragma unroll
        for (int sstep = 0; sstep < 4; ++sstep) {
            uint32_t bfr[8][2];
            #pragma unroll
            for (int nt = 0; nt < 8; ++nt) {
                int d = nt * 8 + grp;
                bfr[nt][0] = sm[OFF_V + (sstep * 8 + thr)     * VP + d];
                bfr[nt][1] = sm[OFF_V + (sstep * 8 + thr + 4) * VP + d];
            }
            #pragma unroll
            for (int at = 0; at < 2; ++at) {
                uint32_t a[4] = {pb[at][2 * sstep][0], pb[at][2 * sstep][1],
                                 pb[at][2 * sstep + 1][0], pb[at][2 * sstep + 1][1]};
                #pragma unroll
                for (int nt = 0; nt < 8; ++nt)
                    MMA_F16(o[at][nt], a, bfr[nt]);
            }
        }
    }

    // Output: [B, S, H*Dh]
    #pragma unroll
    for (int at = 0; at < 2; ++at) {
        #pragma unroll
        for (int half = 0; half < 2; ++half) {
            const int g = at * 2 + half;
            const float inv = 1.f / lrun[g];
            const int q = q0 + wr0 + at * 16 + grp + half * 8;
            #pragma unroll
            for (int nt = 0; nt < 8; ++nt) {
                int d = nt * 8 + 2 * thr;
                float2 v = {o[at][nt][half * 2 + 0] * inv,
                            o[at][nt][half * 2 + 1] * inv};
                *reinterpret_cast<float2*>(
                    &out[((size_t)(b * S_ + q)) * HID + h * D_ + d]) = v;
            }
        }
    }
}

// ---------------------------------------------------------------------------
// Launch
// ---------------------------------------------------------------------------
extern "C" void kernel_launch(void* const* d_in, const int* in_sizes, int n_in,
                              void* d_out, int out_size)
{
    const float* X    = (const float*)d_in[0];
    const float* mask = (const float*)d_in[1];
    const float* Wq   = (const float*)d_in[2];
    const float* bq   = (const float*)d_in[3];
    const float* Wk   = (const float*)d_in[4];
    const float* bk   = (const float*)d_in[5];
    const float* Wv   = (const float*)d_in[6];
    const float* bv   = (const float*)d_in[7];
    float* out = (float*)d_out;

    float *dQ, *dK, *dV;
    cudaGetSymbolAddress((void**)&dQ, g_Q);
    cudaGetSymbolAddress((void**)&dK, g_K);
    cudaGetSymbolAddress((void**)&dV, g_V);

    cudaFuncSetAttribute(qkv_gemm3, cudaFuncAttributeMaxDynamicSharedMemorySize, GEMM_SMEM);
    const int attn_smem = ATTN_WORDS * 4;   // 72192 B
    cudaFuncSetAttribute(attn_f16, cudaFuncAttributeMaxDynamicSharedMemorySize, attn_smem);

    dim3 ggrid(HID / 128, M_ / 128, 3);   // (8, 64, 3)
    qkv_gemm3<<<ggrid, 256, GEMM_SMEM>>>(X, Wq, Wk, Wv, bq, bk, bv, dQ, dK, dV);

    dim3 agrid(S_ / 128, H_, B_);         // (16, 16, 4)
    attn_f16<<<agrid, 128, attn_smem>>>(dQ, dK, dV, mask, out);
}